// round 2
// baseline (speedup 1.0000x reference)
#include <cuda_runtime.h>
#include <cuda_bf16.h>

// Problem constants
#define BATCH   2
#define SEQ     2048
#define HIDDEN  1024
#define HEADS   16
#define HDIM    64
#define NTOK    (BATCH * SEQ)          // 4096
#define QK_SCALE 0.125f                 // 1/sqrt(64)

// ---------------------------------------------------------------------------
// Device scratch (no cudaMalloc allowed)
// ---------------------------------------------------------------------------
__device__ float g_q[BATCH * HEADS * SEQ * HDIM];   // [B,H,S,D] 16 MB
__device__ float g_k[BATCH * HEADS * SEQ * HDIM];
__device__ float g_v[BATCH * HEADS * SEQ * HDIM];
__device__ float g_o[NTOK * HIDDEN];                // [B,S,H*D] 16 MB

// ---------------------------------------------------------------------------
// SGEMM body: C[M=4096, N=1024] = A[4096,1024] @ W[1024,1024]
// 128x128 tile, BK=8, 256 threads, 8x8 per thread.
// permute: scatter C into [B,H,S,D] layout (for Q/K/V); else row-major.
// ---------------------------------------------------------------------------
__device__ __forceinline__ void sgemm_body(
    const float* __restrict__ A, const float* __restrict__ W,
    float* __restrict__ C, int permute)
{
    __shared__ float As[8][128];
    __shared__ float Bs[8][128];

    const int tid  = threadIdx.x;
    const int ty   = tid >> 4;          // 0..15
    const int tx   = tid & 15;          // 0..15
    const int row0 = blockIdx.y * 128;
    const int col0 = blockIdx.x * 128;

    // load indices
    const int a_m  = tid >> 1;          // 0..127
    const int a_k4 = (tid & 1) * 4;     // 0 or 4
    const int b_k  = tid >> 5;          // 0..7
    const int b_n4 = (tid & 31) * 4;    // 0..124

    float acc[8][8];
#pragma unroll
    for (int i = 0; i < 8; i++)
#pragma unroll
        for (int j = 0; j < 8; j++) acc[i][j] = 0.f;

    for (int k0 = 0; k0 < HIDDEN; k0 += 8) {
        // A tile: 128 rows x 8 k, stored transposed As[k][m]
        float4 av = *(const float4*)&A[(row0 + a_m) * HIDDEN + k0 + a_k4];
        As[a_k4 + 0][a_m] = av.x;
        As[a_k4 + 1][a_m] = av.y;
        As[a_k4 + 2][a_m] = av.z;
        As[a_k4 + 3][a_m] = av.w;
        // W tile: 8 k x 128 n
        float4 bv = *(const float4*)&W[(k0 + b_k) * HIDDEN + col0 + b_n4];
        *(float4*)&Bs[b_k][b_n4] = bv;
        __syncthreads();

#pragma unroll
        for (int k = 0; k < 8; k++) {
            float4 a0 = *(const float4*)&As[k][ty * 8];
            float4 a1 = *(const float4*)&As[k][ty * 8 + 4];
            float4 b0 = *(const float4*)&Bs[k][tx * 8];
            float4 b1 = *(const float4*)&Bs[k][tx * 8 + 4];
            float ar[8] = {a0.x, a0.y, a0.z, a0.w, a1.x, a1.y, a1.z, a1.w};
            float br[8] = {b0.x, b0.y, b0.z, b0.w, b1.x, b1.y, b1.z, b1.w};
#pragma unroll
            for (int i = 0; i < 8; i++)
#pragma unroll
                for (int j = 0; j < 8; j++)
                    acc[i][j] = fmaf(ar[i], br[j], acc[i][j]);
        }
        __syncthreads();
    }

    // epilogue
    const int colBase = col0 + tx * 8;
    if (!permute) {
#pragma unroll
        for (int i = 0; i < 8; i++) {
            int row = row0 + ty * 8 + i;
            float4 v0 = make_float4(acc[i][0], acc[i][1], acc[i][2], acc[i][3]);
            float4 v1 = make_float4(acc[i][4], acc[i][5], acc[i][6], acc[i][7]);
            *(float4*)&C[row * HIDDEN + colBase]     = v0;
            *(float4*)&C[row * HIDDEN + colBase + 4] = v1;
        }
    } else {
        // [B,H,S,D]: tx*8 stays inside one 64-wide head
        const int h  = colBase >> 6;
        const int d0 = colBase & 63;
#pragma unroll
        for (int i = 0; i < 8; i++) {
            int row = row0 + ty * 8 + i;
            int b   = row >> 11;            // /2048
            int s   = row & 2047;
            float* dst = &C[(((b * HEADS) + h) * SEQ + s) * HDIM + d0];
            float4 v0 = make_float4(acc[i][0], acc[i][1], acc[i][2], acc[i][3]);
            float4 v1 = make_float4(acc[i][4], acc[i][5], acc[i][6], acc[i][7]);
            *(float4*)&dst[0] = v0;
            *(float4*)&dst[4] = v1;
        }
    }
}

__global__ __launch_bounds__(256) void proj_qkv_kernel(
    const float* __restrict__ X,
    const float* __restrict__ Wq,
    const float* __restrict__ Wk,
    const float* __restrict__ Wv)
{
    const float* W = (blockIdx.z == 0) ? Wq : (blockIdx.z == 1) ? Wk : Wv;
    float* out     = (blockIdx.z == 0) ? g_q : (blockIdx.z == 1) ? g_k : g_v;
    sgemm_body(X, W, out, 1);
}

__global__ __launch_bounds__(256) void proj_out_kernel(
    const float* __restrict__ Wo, float* __restrict__ out)
{
    sgemm_body(g_o, Wo, out, 0);
}

// ---------------------------------------------------------------------------
// Flash attention: one block = 64 q-rows of one (b,h). 256 threads.
// Q,K stored d-major (transposed) with stride 68 (float4-aligned, low conflict).
// P overlaid on K smem buffer after S is computed.
// ---------------------------------------------------------------------------
#define FA_STRIDE 68
#define FA_SMEM_FLOATS (2 * 64 * FA_STRIDE + 64 * 64)
#define FA_SMEM_BYTES  (FA_SMEM_FLOATS * 4)

__global__ __launch_bounds__(256) void flash_kernel()
{
    extern __shared__ float sm[];
    float* Qt = sm;                        // [64][68] d-major
    float* Kt = sm + 64 * FA_STRIDE;       // [64][68] d-major; reused as Ps[qi][kj]
    float* Vs = sm + 2 * 64 * FA_STRIDE;   // [64][64] row-major

    const int tid = threadIdx.x;
    const int ty  = tid >> 4;              // 0..15
    const int tx  = tid & 15;              // 0..15
    const int bh  = blockIdx.y;            // 0..31
    const int q0  = blockIdx.x * 64;

    const float* Qg = g_q + (size_t)bh * SEQ * HDIM;
    const float* Kg = g_k + (size_t)bh * SEQ * HDIM;
    const float* Vg = g_v + (size_t)bh * SEQ * HDIM;

    // load Q (transposed into Qt[d][qi])
    {
        const int rr = tid >> 4;           // 0..15
        const int c4 = (tid & 15) * 4;     // 0..60
#pragma unroll
        for (int it = 0; it < 4; it++) {
            int qi = it * 16 + rr;
            float4 v = *(const float4*)&Qg[(q0 + qi) * HDIM + c4];
            Qt[(c4 + 0) * FA_STRIDE + qi] = v.x;
            Qt[(c4 + 1) * FA_STRIDE + qi] = v.y;
            Qt[(c4 + 2) * FA_STRIDE + qi] = v.z;
            Qt[(c4 + 3) * FA_STRIDE + qi] = v.w;
        }
    }

    float m[4], l[4], o[4][4];
#pragma unroll
    for (int i = 0; i < 4; i++) {
        m[i] = -1e30f; l[i] = 0.f;
#pragma unroll
        for (int j = 0; j < 4; j++) o[i][j] = 0.f;
    }

    const int ntiles = blockIdx.x + 1;     // causal: kv tiles 0..q-tile
    for (int t = 0; t < ntiles; t++) {
        const int j0 = t * 64;
        const bool diag = (t == ntiles - 1);

        // load K (transposed) and V (row-major)
        {
            const int rr = tid >> 4;
            const int c4 = (tid & 15) * 4;
#pragma unroll
            for (int it = 0; it < 4; it++) {
                int kj = it * 16 + rr;
                float4 kv = *(const float4*)&Kg[(j0 + kj) * HDIM + c4];
                Kt[(c4 + 0) * FA_STRIDE + kj] = kv.x;
                Kt[(c4 + 1) * FA_STRIDE + kj] = kv.y;
                Kt[(c4 + 2) * FA_STRIDE + kj] = kv.z;
                Kt[(c4 + 3) * FA_STRIDE + kj] = kv.w;
                float4 vv = *(const float4*)&Vg[(j0 + kj) * HDIM + c4];
                *(float4*)&Vs[kj * 64 + c4] = vv;
            }
        }
        __syncthreads();

        // S = Q K^T
        float sc[4][4];
#pragma unroll
        for (int i = 0; i < 4; i++)
#pragma unroll
            for (int j = 0; j < 4; j++) sc[i][j] = 0.f;

#pragma unroll
        for (int d = 0; d < 64; d++) {
            float4 qa = *(const float4*)&Qt[d * FA_STRIDE + ty * 4];
            float4 kb = *(const float4*)&Kt[d * FA_STRIDE + tx * 4];
            float qr[4] = {qa.x, qa.y, qa.z, qa.w};
            float kr[4] = {kb.x, kb.y, kb.z, kb.w};
#pragma unroll
            for (int i = 0; i < 4; i++)
#pragma unroll
                for (int j = 0; j < 4; j++)
                    sc[i][j] = fmaf(qr[i], kr[j], sc[i][j]);
        }

        // scale + causal mask (diag tile only)
#pragma unroll
        for (int i = 0; i < 4; i++) {
            int qrow = q0 + ty * 4 + i;
#pragma unroll
            for (int j = 0; j < 4; j++) {
                float v = sc[i][j] * QK_SCALE;
                if (diag) {
                    int kcol = j0 + tx * 4 + j;
                    if (kcol > qrow) v = -1e9f;
                }
                sc[i][j] = v;
            }
        }

        // online softmax: row max / sum across the 16 tx lanes of each row
        float mnew[4], alpha[4], rs[4];
#pragma unroll
        for (int i = 0; i < 4; i++) {
            float mm = fmaxf(fmaxf(sc[i][0], sc[i][1]), fmaxf(sc[i][2], sc[i][3]));
#pragma unroll
            for (int off = 8; off >= 1; off >>= 1)
                mm = fmaxf(mm, __shfl_xor_sync(0xffffffffu, mm, off));
            mnew[i]  = fmaxf(m[i], mm);
            alpha[i] = __expf(m[i] - mnew[i]);
            float r = 0.f;
#pragma unroll
            for (int j = 0; j < 4; j++) {
                float p = __expf(sc[i][j] - mnew[i]);
                sc[i][j] = p;
                r += p;
            }
#pragma unroll
            for (int off = 8; off >= 1; off >>= 1)
                r += __shfl_xor_sync(0xffffffffu, r, off);
            rs[i] = r;
        }
#pragma unroll
        for (int i = 0; i < 4; i++) {
            l[i] = l[i] * alpha[i] + rs[i];
            m[i] = mnew[i];
#pragma unroll
            for (int j = 0; j < 4; j++) o[i][j] *= alpha[i];
        }

        __syncthreads();   // everyone done reading Kt; safe to overwrite with P
        float* Ps = Kt;
#pragma unroll
        for (int i = 0; i < 4; i++)
#pragma unroll
            for (int j = 0; j < 4; j++)
                Ps[(ty * 4 + i) * FA_STRIDE + (tx * 4 + j)] = sc[i][j];
        __syncthreads();

        // O += P @ V  (thread: rows ty*4.., cols tx*4..)
#pragma unroll 8
        for (int kj = 0; kj < 64; kj++) {
            float4 vb = *(const float4*)&Vs[kj * 64 + tx * 4];
            float vr[4] = {vb.x, vb.y, vb.z, vb.w};
            float pr[4];
#pragma unroll
            for (int i = 0; i < 4; i++)
                pr[i] = Ps[(ty * 4 + i) * FA_STRIDE + kj];
#pragma unroll
            for (int i = 0; i < 4; i++)
#pragma unroll
                for (int j = 0; j < 4; j++)
                    o[i][j] = fmaf(pr[i], vr[j], o[i][j]);
        }
        __syncthreads();   // before next tile overwrites Kt/Vs
    }

    // epilogue: normalize, write g_o[b][s][h*64+d]
    const int b = bh >> 4;
    const int h = bh & 15;
#pragma unroll
    for (int i = 0; i < 4; i++) {
        float inv = 1.0f / l[i];
        int s = q0 + ty * 4 + i;
        float* dst = &g_o[((size_t)(b * SEQ) + s) * HIDDEN + h * HDIM + tx * 4];
        float4 v = make_float4(o[i][0] * inv, o[i][1] * inv, o[i][2] * inv, o[i][3] * inv);
        *(float4*)dst = v;
    }
}

// ---------------------------------------------------------------------------
// Launch
// ---------------------------------------------------------------------------
extern "C" void kernel_launch(void* const* d_in, const int* in_sizes, int n_in,
                              void* d_out, int out_size)
{
    const float* X  = (const float*)d_in[0];   // hidden_states [2,2048,1024]
    // d_in[1] = attention_mask (exact causal; applied analytically in-kernel)
    const float* Wq = (const float*)d_in[2];
    const float* Wk = (const float*)d_in[3];
    const float* Wv = (const float*)d_in[4];
    const float* Wo = (const float*)d_in[5];
    float* out = (float*)d_out;

    dim3 gProj(HIDDEN / 128, NTOK / 128, 3);   // (8, 32, 3)
    proj_qkv_kernel<<<gProj, 256>>>(X, Wq, Wk, Wv);

    // 50 KB dynamic smem needs the opt-in attribute (immediate host API; not
    // a stream op, legal under graph capture).
    cudaFuncSetAttribute(flash_kernel,
                         cudaFuncAttributeMaxDynamicSharedMemorySize, FA_SMEM_BYTES);
    dim3 gFa(SEQ / 64, BATCH * HEADS);         // (32, 32)
    flash_kernel<<<gFa, 256, FA_SMEM_BYTES>>>();

    dim3 gOut(HIDDEN / 128, NTOK / 128, 1);    // (8, 32)
    proj_out_kernel<<<gOut, 256>>>(Wo, out);
}

// round 4
// speedup vs baseline: 1.0000x; 1.0000x over previous
#include <cuda_runtime.h>
#include <cuda_bf16.h>
#include <cstdint>

// Problem constants
#define BATCH   2
#define SEQ     2048
#define HIDDEN  1024
#define HEADS   16
#define HDIM    64
#define NTOK    (BATCH * SEQ)          // 4096
#define QK_SCALE 0.125f                 // 1/sqrt(64)

// ---------------------------------------------------------------------------
// Device scratch (no cudaMalloc allowed)
// ---------------------------------------------------------------------------
__device__ float g_q[BATCH * HEADS * SEQ * HDIM];   // [B,H,S,D]
__device__ float g_k[BATCH * HEADS * SEQ * HDIM];
__device__ float g_v[BATCH * HEADS * SEQ * HDIM];
__device__ float g_o[NTOK * HIDDEN];                // [B,S,H*D]

// ---------------------------------------------------------------------------
// mma.sync bf16 (sm_80+ baseline; works at compute_100)
// D[16x8] += A[16x16] * B[16x8], A row-major, B col-major, fp32 accum
// ---------------------------------------------------------------------------
__device__ __forceinline__ void mma_bf16(float d[4], const uint32_t a[4], const uint32_t b[2]) {
    asm volatile(
        "mma.sync.aligned.m16n8k16.row.col.f32.bf16.bf16.f32 "
        "{%0,%1,%2,%3}, {%4,%5,%6,%7}, {%8,%9}, {%0,%1,%2,%3};"
        : "+f"(d[0]), "+f"(d[1]), "+f"(d[2]), "+f"(d[3])
        : "r"(a[0]), "r"(a[1]), "r"(a[2]), "r"(a[3]), "r"(b[0]), "r"(b[1]));
}

__device__ __forceinline__ void cvt_hilo(float x, unsigned short& hi, unsigned short& lo) {
    __nv_bfloat16 h = __float2bfloat16_rn(x);
    float r = x - __bfloat162float(h);
    __nv_bfloat16 l = __float2bfloat16_rn(r);
    hi = __bfloat16_as_ushort(h);
    lo = __bfloat16_as_ushort(l);
}

// ---------------------------------------------------------------------------
// Split-bf16 tensor-core GEMM: C[4096 x 1024] = A[4096 x 1024] @ W[1024 x 1024]
// Block tile 128x128, BK=32, 256 threads (8 warps, warp tile 64x32).
// Double-buffered smem, register-staged global loads.
// mode 0: C row-major.  mode 1: scatter into [B,H,S,D] (QKV).
// ---------------------------------------------------------------------------
#define BKK      32
#define KITERS   (HIDDEN / BKK)         // 32
#define ASTRIDE  40                     // bf16 elems per smem row (pad: conflict-free frags)
#define TILE_B   (128 * ASTRIDE * 2)    // 10240 bytes per matrix tile
#define STAGE_B  (4 * TILE_B)           // A_hi, A_lo, B_hi, B_lo
#define GEMM_SMEM (2 * STAGE_B)         // 81920 bytes
#define OFF_AHI  0
#define OFF_ALO  TILE_B
#define OFF_BHI  (2 * TILE_B)
#define OFF_BLO  (3 * TILE_B)
#define SOFF(r, k) ((uint32_t)(((r) * ASTRIDE + (k)) * 2))

__device__ __forceinline__ void gemm_tc_body(
    const float* __restrict__ A, const float* __restrict__ W,
    float* __restrict__ C, int mode)
{
    extern __shared__ __align__(16) char smem[];

    const int tid    = threadIdx.x;
    const int wid    = tid >> 5;
    const int lane   = tid & 31;
    const int g      = lane >> 2;       // groupID 0..7
    const int tig    = lane & 3;        // thread-in-group
    const int warp_m = wid >> 2;        // 0..1
    const int warp_n = wid & 3;         // 0..3
    const int row0   = blockIdx.y * 128;
    const int col0   = blockIdx.x * 128;

    float acc[4][4][4];
#pragma unroll
    for (int mi = 0; mi < 4; mi++)
#pragma unroll
        for (int ni = 0; ni < 4; ni++)
#pragma unroll
            for (int e = 0; e < 4; e++) acc[mi][ni][e] = 0.f;

    float4 aReg[4], bReg[4];

    // ---- global load of stage kc into registers ----
    auto loadGlobal = [&](int kc) {
        const int k0 = kc * BKK;
#pragma unroll
        for (int i = 0; i < 4; i++) {
            int idx = i * 256 + tid;            // 1024 float4 for A tile
            int r   = idx >> 3;                 // 0..127
            int c4  = (idx & 7) * 4;            // 0..28
            aReg[i] = *(const float4*)&A[(size_t)(row0 + r) * HIDDEN + k0 + c4];
        }
#pragma unroll
        for (int i = 0; i < 4; i++) {
            int idx = i * 256 + tid;
            int kr  = idx >> 5;                 // 0..31
            int n4  = (idx & 31) * 4;           // 0..124
            bReg[i] = *(const float4*)&W[(size_t)(k0 + kr) * HIDDEN + col0 + n4];
        }
    };

    // ---- convert + store registers into smem buffer ----
    auto storeSmem = [&](int buf) {
        char* a_hi = smem + buf * STAGE_B + OFF_AHI;
        char* a_lo = smem + buf * STAGE_B + OFF_ALO;
        char* b_hi = smem + buf * STAGE_B + OFF_BHI;
        char* b_lo = smem + buf * STAGE_B + OFF_BLO;
#pragma unroll
        for (int i = 0; i < 4; i++) {
            int idx = i * 256 + tid;
            int r   = idx >> 3;
            int c4  = (idx & 7) * 4;
            unsigned short h0, h1, h2, h3, l0, l1, l2, l3;
            cvt_hilo(aReg[i].x, h0, l0); cvt_hilo(aReg[i].y, h1, l1);
            cvt_hilo(aReg[i].z, h2, l2); cvt_hilo(aReg[i].w, h3, l3);
            uint32_t off = SOFF(r, c4);
            *(uint2*)(a_hi + off) = make_uint2((uint32_t)h0 | ((uint32_t)h1 << 16),
                                               (uint32_t)h2 | ((uint32_t)h3 << 16));
            *(uint2*)(a_lo + off) = make_uint2((uint32_t)l0 | ((uint32_t)l1 << 16),
                                               (uint32_t)l2 | ((uint32_t)l3 << 16));
        }
#pragma unroll
        for (int i = 0; i < 4; i++) {
            int idx = i * 256 + tid;
            int kr  = idx >> 5;
            int n4  = (idx & 31) * 4;
            float vals[4] = {bReg[i].x, bReg[i].y, bReg[i].z, bReg[i].w};
#pragma unroll
            for (int j = 0; j < 4; j++) {
                unsigned short h, l;
                cvt_hilo(vals[j], h, l);
                uint32_t off = SOFF(n4 + j, kr);
                *(unsigned short*)(b_hi + off) = h;
                *(unsigned short*)(b_lo + off) = l;
            }
        }
    };

    // ---- compute one stage from smem buffer ----
    auto compute = [&](int buf) {
        char* Ahi = smem + buf * STAGE_B + OFF_AHI;
        char* Alo = smem + buf * STAGE_B + OFF_ALO;
        char* Bhi = smem + buf * STAGE_B + OFF_BHI;
        char* Blo = smem + buf * STAGE_B + OFF_BLO;
#pragma unroll
        for (int ks = 0; ks < BKK; ks += 16) {
            uint32_t ah[4][4], al[4][4], bh[4][2], bl[4][2];
            const int kk = ks + tig * 2;
#pragma unroll
            for (int mi = 0; mi < 4; mi++) {
                int r = warp_m * 64 + mi * 16 + g;
                ah[mi][0] = *(const uint32_t*)(Ahi + SOFF(r,     kk));
                ah[mi][1] = *(const uint32_t*)(Ahi + SOFF(r + 8, kk));
                ah[mi][2] = *(const uint32_t*)(Ahi + SOFF(r,     kk + 8));
                ah[mi][3] = *(const uint32_t*)(Ahi + SOFF(r + 8, kk + 8));
                al[mi][0] = *(const uint32_t*)(Alo + SOFF(r,     kk));
                al[mi][1] = *(const uint32_t*)(Alo + SOFF(r + 8, kk));
                al[mi][2] = *(const uint32_t*)(Alo + SOFF(r,     kk + 8));
                al[mi][3] = *(const uint32_t*)(Alo + SOFF(r + 8, kk + 8));
            }
#pragma unroll
            for (int ni = 0; ni < 4; ni++) {
                int n = warp_n * 32 + ni * 8 + g;
                bh[ni][0] = *(const uint32_t*)(Bhi + SOFF(n, kk));
                bh[ni][1] = *(const uint32_t*)(Bhi + SOFF(n, kk + 8));
                bl[ni][0] = *(const uint32_t*)(Blo + SOFF(n, kk));
                bl[ni][1] = *(const uint32_t*)(Blo + SOFF(n, kk + 8));
            }
#pragma unroll
            for (int mi = 0; mi < 4; mi++)
#pragma unroll
                for (int ni = 0; ni < 4; ni++) {
                    mma_bf16(acc[mi][ni], ah[mi], bh[ni]);
                    mma_bf16(acc[mi][ni], ah[mi], bl[ni]);
                    mma_bf16(acc[mi][ni], al[mi], bh[ni]);
                }
        }
    };

    // ---- pipelined main loop ----
    loadGlobal(0);
    storeSmem(0);
    __syncthreads();
    for (int kc = 0; kc < KITERS; kc++) {
        if (kc + 1 < KITERS) loadGlobal(kc + 1);
        compute(kc & 1);
        if (kc + 1 < KITERS) {
            storeSmem((kc + 1) & 1);
            __syncthreads();
        }
    }

    // ---- epilogue ----
#pragma unroll
    for (int mi = 0; mi < 4; mi++) {
        int r0g = row0 + warp_m * 64 + mi * 16 + g;   // rows r0g and r0g+8
#pragma unroll
        for (int ni = 0; ni < 4; ni++) {
            int col = col0 + warp_n * 32 + ni * 8 + tig * 2;
            if (mode == 0) {
                *(float2*)&C[(size_t)r0g * HIDDEN + col] =
                    make_float2(acc[mi][ni][0], acc[mi][ni][1]);
                *(float2*)&C[(size_t)(r0g + 8) * HIDDEN + col] =
                    make_float2(acc[mi][ni][2], acc[mi][ni][3]);
            } else {
                int h = col >> 6, d = col & 63;
                int b0b = r0g >> 11, s0 = r0g & 2047;
                int b1b = (r0g + 8) >> 11, s1 = (r0g + 8) & 2047;
                *(float2*)&C[(((size_t)(b0b * HEADS + h)) * SEQ + s0) * HDIM + d] =
                    make_float2(acc[mi][ni][0], acc[mi][ni][1]);
                *(float2*)&C[(((size_t)(b1b * HEADS + h)) * SEQ + s1) * HDIM + d] =
                    make_float2(acc[mi][ni][2], acc[mi][ni][3]);
            }
        }
    }
}

__global__ __launch_bounds__(256) void proj_qkv_tc(
    const float* __restrict__ X,
    const float* __restrict__ Wq,
    const float* __restrict__ Wk,
    const float* __restrict__ Wv)
{
    const float* W = (blockIdx.z == 0) ? Wq : (blockIdx.z == 1) ? Wk : Wv;
    float* out     = (blockIdx.z == 0) ? g_q : (blockIdx.z == 1) ? g_k : g_v;
    gemm_tc_body(X, W, out, 1);
}

__global__ __launch_bounds__(256) void proj_out_tc(
    const float* __restrict__ Wo, float* __restrict__ out)
{
    gemm_tc_body(g_o, Wo, out, 0);
}

// ---------------------------------------------------------------------------
// Flash attention (fp32, unchanged from passing round)
// ---------------------------------------------------------------------------
#define FA_STRIDE 68
#define FA_SMEM_FLOATS (2 * 64 * FA_STRIDE + 64 * 64)
#define FA_SMEM_BYTES  (FA_SMEM_FLOATS * 4)

__global__ __launch_bounds__(256) void flash_kernel()
{
    extern __shared__ float sm[];
    float* Qt = sm;
    float* Kt = sm + 64 * FA_STRIDE;
    float* Vs = sm + 2 * 64 * FA_STRIDE;

    const int tid = threadIdx.x;
    const int ty  = tid >> 4;
    const int tx  = tid & 15;
    const int bh  = blockIdx.y;
    const int q0  = blockIdx.x * 64;

    const float* Qg = g_q + (size_t)bh * SEQ * HDIM;
    const float* Kg = g_k + (size_t)bh * SEQ * HDIM;
    const float* Vg = g_v + (size_t)bh * SEQ * HDIM;

    {
        const int rr = tid >> 4;
        const int c4 = (tid & 15) * 4;
#pragma unroll
        for (int it = 0; it < 4; it++) {
            int qi = it * 16 + rr;
            float4 v = *(const float4*)&Qg[(q0 + qi) * HDIM + c4];
            Qt[(c4 + 0) * FA_STRIDE + qi] = v.x;
            Qt[(c4 + 1) * FA_STRIDE + qi] = v.y;
            Qt[(c4 + 2) * FA_STRIDE + qi] = v.z;
            Qt[(c4 + 3) * FA_STRIDE + qi] = v.w;
        }
    }

    float m[4], l[4], o[4][4];
#pragma unroll
    for (int i = 0; i < 4; i++) {
        m[i] = -1e30f; l[i] = 0.f;
#pragma unroll
        for (int j = 0; j < 4; j++) o[i][j] = 0.f;
    }

    const int ntiles = blockIdx.x + 1;
    for (int t = 0; t < ntiles; t++) {
        const int j0 = t * 64;
        const bool diag = (t == ntiles - 1);

        {
            const int rr = tid >> 4;
            const int c4 = (tid & 15) * 4;
#pragma unroll
            for (int it = 0; it < 4; it++) {
                int kj = it * 16 + rr;
                float4 kv = *(const float4*)&Kg[(j0 + kj) * HDIM + c4];
                Kt[(c4 + 0) * FA_STRIDE + kj] = kv.x;
                Kt[(c4 + 1) * FA_STRIDE + kj] = kv.y;
                Kt[(c4 + 2) * FA_STRIDE + kj] = kv.z;
                Kt[(c4 + 3) * FA_STRIDE + kj] = kv.w;
                float4 vv = *(const float4*)&Vg[(j0 + kj) * HDIM + c4];
                *(float4*)&Vs[kj * 64 + c4] = vv;
            }
        }
        __syncthreads();

        float sc[4][4];
#pragma unroll
        for (int i = 0; i < 4; i++)
#pragma unroll
            for (int j = 0; j < 4; j++) sc[i][j] = 0.f;

#pragma unroll
        for (int d = 0; d < 64; d++) {
            float4 qa = *(const float4*)&Qt[d * FA_STRIDE + ty * 4];
            float4 kb = *(const float4*)&Kt[d * FA_STRIDE + tx * 4];
            float qr[4] = {qa.x, qa.y, qa.z, qa.w};
            float kr[4] = {kb.x, kb.y, kb.z, kb.w};
#pragma unroll
            for (int i = 0; i < 4; i++)
#pragma unroll
                for (int j = 0; j < 4; j++)
                    sc[i][j] = fmaf(qr[i], kr[j], sc[i][j]);
        }

#pragma unroll
        for (int i = 0; i < 4; i++) {
            int qrow = q0 + ty * 4 + i;
#pragma unroll
            for (int j = 0; j < 4; j++) {
                float v = sc[i][j] * QK_SCALE;
                if (diag) {
                    int kcol = j0 + tx * 4 + j;
                    if (kcol > qrow) v = -1e9f;
                }
                sc[i][j] = v;
            }
        }

        float mnew[4], alpha[4], rs[4];
#pragma unroll
        for (int i = 0; i < 4; i++) {
            float mm = fmaxf(fmaxf(sc[i][0], sc[i][1]), fmaxf(sc[i][2], sc[i][3]));
#pragma unroll
            for (int off = 8; off >= 1; off >>= 1)
                mm = fmaxf(mm, __shfl_xor_sync(0xffffffffu, mm, off));
            mnew[i]  = fmaxf(m[i], mm);
            alpha[i] = __expf(m[i] - mnew[i]);
            float r = 0.f;
#pragma unroll
            for (int j = 0; j < 4; j++) {
                float p = __expf(sc[i][j] - mnew[i]);
                sc[i][j] = p;
                r += p;
            }
#pragma unroll
            for (int off = 8; off >= 1; off >>= 1)
                r += __shfl_xor_sync(0xffffffffu, r, off);
            rs[i] = r;
        }
#pragma unroll
        for (int i = 0; i < 4; i++) {
            l[i] = l[i] * alpha[i] + rs[i];
            m[i] = mnew[i];
#pragma unroll
            for (int j = 0; j < 4; j++) o[i][j] *= alpha[i];
        }

        __syncthreads();
        float* Ps = Kt;
#pragma unroll
        for (int i = 0; i < 4; i++)
#pragma unroll
            for (int j = 0; j < 4; j++)
                Ps[(ty * 4 + i) * FA_STRIDE + (tx * 4 + j)] = sc[i][j];
        __syncthreads();

#pragma unroll 8
        for (int kj = 0; kj < 64; kj++) {
            float4 vb = *(const float4*)&Vs[kj * 64 + tx * 4];
            float vr[4] = {vb.x, vb.y, vb.z, vb.w};
            float pr[4];
#pragma unroll
            for (int i = 0; i < 4; i++)
                pr[i] = Ps[(ty * 4 + i) * FA_STRIDE + kj];
#pragma unroll
            for (int i = 0; i < 4; i++)
#pragma unroll
                for (int j = 0; j < 4; j++)
                    o[i][j] = fmaf(pr[i], vr[j], o[i][j]);
        }
        __syncthreads();
    }

    const int b = bh >> 4;
    const int h = bh & 15;
#pragma unroll
    for (int i = 0; i < 4; i++) {
        float inv = 1.0f / l[i];
        int s = q0 + ty * 4 + i;
        float* dst = &g_o[((size_t)(b * SEQ) + s) * HIDDEN + h * HDIM + tx * 4];
        float4 v = make_float4(o[i][0] * inv, o[i][1] * inv, o[i][2] * inv, o[i][3] * inv);
        *(float4*)dst = v;
    }
}

// ---------------------------------------------------------------------------
// Launch
// ---------------------------------------------------------------------------
extern "C" void kernel_launch(void* const* d_in, const int* in_sizes, int n_in,
                              void* d_out, int out_size)
{
    const float* X  = (const float*)d_in[0];   // hidden_states [2,2048,1024]
    // d_in[1] = attention_mask (exact causal; applied analytically in-kernel)
    const float* Wq = (const float*)d_in[2];
    const float* Wk = (const float*)d_in[3];
    const float* Wv = (const float*)d_in[4];
    const float* Wo = (const float*)d_in[5];
    float* out = (float*)d_out;

    cudaFuncSetAttribute(proj_qkv_tc,
                         cudaFuncAttributeMaxDynamicSharedMemorySize, GEMM_SMEM);
    cudaFuncSetAttribute(proj_out_tc,
                         cudaFuncAttributeMaxDynamicSharedMemorySize, GEMM_SMEM);
    cudaFuncSetAttribute(flash_kernel,
                         cudaFuncAttributeMaxDynamicSharedMemorySize, FA_SMEM_BYTES);

    dim3 gProj(HIDDEN / 128, NTOK / 128, 3);   // (8, 32, 3)
    proj_qkv_tc<<<gProj, 256, GEMM_SMEM>>>(X, Wq, Wk, Wv);

    dim3 gFa(SEQ / 64, BATCH * HEADS);         // (32, 32)
    flash_kernel<<<gFa, 256, FA_SMEM_BYTES>>>();

    dim3 gOut(HIDDEN / 128, NTOK / 128, 1);    // (8, 32)
    proj_out_tc<<<gOut, 256, GEMM_SMEM>>>(Wo, out);
}

// round 6
// speedup vs baseline: 2.6028x; 2.6027x over previous
#include <cuda_runtime.h>
#include <cuda_bf16.h>
#include <cstdint>

#define BATCH   2
#define SEQ     2048
#define HIDDEN  1024
#define HEADS   16
#define HDIM    64
#define NTOK    (BATCH * SEQ)          // 4096
#define QK_SCALE 0.125f

typedef __nv_bfloat16 bf16;

// ---------------------------------------------------------------------------
// Device scratch (no cudaMalloc allowed)
// ---------------------------------------------------------------------------
__device__ bf16 s_xhi[NTOK * HIDDEN];               // X split-bf16
__device__ bf16 s_xlo[NTOK * HIDDEN];
__device__ bf16 s_whi[4 * HIDDEN * HIDDEN];         // W^T split-bf16 (q,k,v,o)
__device__ bf16 s_wlo[4 * HIDDEN * HIDDEN];
__device__ bf16 g_qhi[BATCH * HEADS * SEQ * HDIM];  // [B,H,S,D]
__device__ bf16 g_qlo[BATCH * HEADS * SEQ * HDIM];
__device__ bf16 g_khi[BATCH * HEADS * SEQ * HDIM];
__device__ bf16 g_klo[BATCH * HEADS * SEQ * HDIM];
__device__ bf16 g_vhi[BATCH * HEADS * SEQ * HDIM];
__device__ bf16 g_vlo[BATCH * HEADS * SEQ * HDIM];
__device__ bf16 g_ohi[NTOK * HIDDEN];               // attention out [B,S,H*D]
__device__ bf16 g_olo[NTOK * HIDDEN];

// ---------------------------------------------------------------------------
// PTX helpers
// ---------------------------------------------------------------------------
__device__ __forceinline__ uint32_t smem_u32(const void* p) {
    uint32_t a;
    asm("{ .reg .u64 t; cvta.to.shared.u64 t, %1; cvt.u32.u64 %0, t; }" : "=r"(a) : "l"(p));
    return a;
}
__device__ __forceinline__ void cp16(uint32_t s, const void* g) {
    asm volatile("cp.async.cg.shared.global [%0], [%1], 16;" :: "r"(s), "l"(g) : "memory");
}
#define CP_COMMIT() asm volatile("cp.async.commit_group;" ::: "memory")
#define CP_WAIT1()  asm volatile("cp.async.wait_group 1;" ::: "memory")
#define CP_WAIT2()  asm volatile("cp.async.wait_group 2;" ::: "memory")

__device__ __forceinline__ void ldsm4(uint32_t& r0, uint32_t& r1, uint32_t& r2, uint32_t& r3, uint32_t a) {
    asm volatile("ldmatrix.sync.aligned.m8n8.x4.shared.b16 {%0,%1,%2,%3}, [%4];"
                 : "=r"(r0), "=r"(r1), "=r"(r2), "=r"(r3) : "r"(a));
}
__device__ __forceinline__ void ldsm4t(uint32_t& r0, uint32_t& r1, uint32_t& r2, uint32_t& r3, uint32_t a) {
    asm volatile("ldmatrix.sync.aligned.m8n8.x4.trans.shared.b16 {%0,%1,%2,%3}, [%4];"
                 : "=r"(r0), "=r"(r1), "=r"(r2), "=r"(r3) : "r"(a));
}
__device__ __forceinline__ void mma_bf16(float d[4], const uint32_t a[4], const uint32_t b[2]) {
    asm volatile(
        "mma.sync.aligned.m16n8k16.row.col.f32.bf16.bf16.f32 "
        "{%0,%1,%2,%3}, {%4,%5,%6,%7}, {%8,%9}, {%0,%1,%2,%3};"
        : "+f"(d[0]), "+f"(d[1]), "+f"(d[2]), "+f"(d[3])
        : "r"(a[0]), "r"(a[1]), "r"(a[2]), "r"(a[3]), "r"(b[0]), "r"(b[1]));
}
// split x,y into packed bf16 hi pair + lo pair
__device__ __forceinline__ void hilo2(float x, float y, uint32_t& hi, uint32_t& lo) {
    __nv_bfloat16 hx = __float2bfloat16_rn(x), hy = __float2bfloat16_rn(y);
    float rx = x - __bfloat162float(hx), ry = y - __bfloat162float(hy);
    __nv_bfloat16 lx = __float2bfloat16_rn(rx), ly = __float2bfloat16_rn(ry);
    hi = (uint32_t)__bfloat16_as_ushort(hx) | ((uint32_t)__bfloat16_as_ushort(hy) << 16);
    lo = (uint32_t)__bfloat16_as_ushort(lx) | ((uint32_t)__bfloat16_as_ushort(ly) << 16);
}

// ---------------------------------------------------------------------------
// Pre-convert kernels
// ---------------------------------------------------------------------------
__global__ __launch_bounds__(256) void convert_x(const float* __restrict__ X) {
    size_t i4 = ((size_t)blockIdx.x * 256 + threadIdx.x) * 4;
    float4 v = *(const float4*)&X[i4];
    uint32_t h0, l0, h1, l1;
    hilo2(v.x, v.y, h0, l0);
    hilo2(v.z, v.w, h1, l1);
    *(uint32_t*)&s_xhi[i4]     = h0;  *(uint32_t*)&s_xhi[i4 + 2] = h1;
    *(uint32_t*)&s_xlo[i4]     = l0;  *(uint32_t*)&s_xlo[i4 + 2] = l1;
}

// W [k][n] -> Wt [n][k] split-bf16, 32x32 tiles
__global__ __launch_bounds__(256) void transpose_w(
    const float* __restrict__ w0, const float* __restrict__ w1,
    const float* __restrict__ w2, const float* __restrict__ w3)
{
    __shared__ float t[32][33];
    const int z = blockIdx.z;
    const float* W = (z == 0) ? w0 : (z == 1) ? w1 : (z == 2) ? w2 : w3;
    const size_t zoff = (size_t)z * HIDDEN * HIDDEN;
    const int n0 = blockIdx.x * 32, k0 = blockIdx.y * 32;
    const int tx = threadIdx.x, ty = threadIdx.y;   // 32 x 8
#pragma unroll
    for (int i = 0; i < 4; i++)
        t[ty + i * 8][tx] = W[(size_t)(k0 + ty + i * 8) * HIDDEN + n0 + tx];
    __syncthreads();
#pragma unroll
    for (int i = 0; i < 4; i++) {
        int nr = ty + i * 8;
        float v = t[tx][nr];
        bf16 h = __float2bfloat16_rn(v);
        bf16 l = __float2bfloat16_rn(v - __bfloat162float(h));
        s_whi[zoff + (size_t)(n0 + nr) * HIDDEN + k0 + tx] = h;
        s_wlo[zoff + (size_t)(n0 + nr) * HIDDEN + k0 + tx] = l;
    }
}

// ---------------------------------------------------------------------------
// Split-bf16 GEMM: C[4096x1024] = A @ Wt^T ; A,Wt row-major bf16 hi/lo.
// 128x128x32 tiles, 4-stage cp.async, ldmatrix, 256 threads (8 warps 64x32).
// ---------------------------------------------------------------------------
#define GBK     32
#define GKITERS (HIDDEN / GBK)          // 32
#define GSTR    80                      // bytes per smem row (40 bf16, pad)
#define GT_B    (128 * GSTR)            // 10240 per matrix tile
#define OA_HI   0
#define OA_LO   GT_B
#define OB_HI   (2 * GT_B)
#define OB_LO   (3 * GT_B)
#define GSTAGE_B (4 * GT_B)             // 40960
#define GNSTAGE 4
#define GSMEM   (GNSTAGE * GSTAGE_B)    // 163840

__device__ __forceinline__ void gemm_load_stage(
    uint32_t sb, const bf16* __restrict__ Ahi, const bf16* __restrict__ Alo,
    const bf16* __restrict__ Bhi, const bf16* __restrict__ Blo,
    int row0, int col0, int kc, int tid)
{
    const int k0 = kc * GBK;
#pragma unroll
    for (int i = 0; i < 2; i++) {
        int idx = tid + i * 256;        // 512 chunks per matrix
        int r = idx >> 2, c = idx & 3;  // r 0..127, c 0..3 (16B chunks)
        uint32_t so = (uint32_t)(r * GSTR + c * 16);
        size_t ga = (size_t)(row0 + r) * HIDDEN + k0 + c * 8;
        size_t gb = (size_t)(col0 + r) * HIDDEN + k0 + c * 8;
        cp16(sb + OA_HI + so, &Ahi[ga]);
        cp16(sb + OA_LO + so, &Alo[ga]);
        cp16(sb + OB_HI + so, &Bhi[gb]);
        cp16(sb + OB_LO + so, &Blo[gb]);
    }
}

__device__ __forceinline__ void gemm_body(
    const bf16* __restrict__ Ahi, const bf16* __restrict__ Alo,
    const bf16* __restrict__ Bhi, const bf16* __restrict__ Blo,
    bf16* __restrict__ OutHi, bf16* __restrict__ OutLo,   // mode qkv (permuted)
    float* __restrict__ OutF)                             // mode fp32 row-major
{
    extern __shared__ __align__(16) char gsm[];
    const uint32_t sb0 = smem_u32(gsm);

    const int tid = threadIdx.x;
    const int lane = tid & 31;
    const int wid = tid >> 5;
    const int g = lane >> 2, tig = lane & 3;
    const int warp_m = wid >> 2, warp_n = wid & 3;
    const int row0 = blockIdx.y * 128;
    const int col0 = blockIdx.x * 128;

    float acc[4][4][4];
#pragma unroll
    for (int mi = 0; mi < 4; mi++)
#pragma unroll
        for (int ni = 0; ni < 4; ni++)
#pragma unroll
            for (int e = 0; e < 4; e++) acc[mi][ni][e] = 0.f;

    // prologue: stages 0..2
    for (int p = 0; p < 3; p++) {
        gemm_load_stage(sb0 + p * GSTAGE_B, Ahi, Alo, Bhi, Blo, row0, col0, p, tid);
        CP_COMMIT();
    }

    // fragment address components (constant per thread)
    const uint32_t a_row = (uint32_t)(((lane >> 3) & 1) * 8 + (lane & 7));
    const uint32_t a_cb  = (uint32_t)((lane >> 4) * 16);
    const uint32_t b_row = (uint32_t)((lane >> 4) * 8 + (lane & 7));
    const uint32_t b_cb  = (uint32_t)(((lane >> 3) & 1) * 16);

    for (int kc = 0; kc < GKITERS; kc++) {
        CP_WAIT2();
        __syncthreads();
        if (kc + 3 < GKITERS)
            gemm_load_stage(sb0 + ((kc + 3) & 3) * GSTAGE_B, Ahi, Alo, Bhi, Blo,
                            row0, col0, kc + 3, tid);
        CP_COMMIT();

        const uint32_t sb = sb0 + (kc & 3) * GSTAGE_B;
#pragma unroll
        for (int ks = 0; ks < 2; ks++) {           // two k16 slices
            const uint32_t cbA = (uint32_t)(ks * 32) + a_cb;
            const uint32_t cbB = (uint32_t)(ks * 32) + b_cb;
            uint32_t ah[4][4], al[4][4];
#pragma unroll
            for (int mi = 0; mi < 4; mi++) {
                uint32_t r = (uint32_t)(warp_m * 64 + mi * 16) + a_row;
                uint32_t ad = sb + r * GSTR + cbA;
                ldsm4(ah[mi][0], ah[mi][1], ah[mi][2], ah[mi][3], ad + OA_HI);
                ldsm4(al[mi][0], al[mi][1], al[mi][2], al[mi][3], ad + OA_LO);
            }
#pragma unroll
            for (int np = 0; np < 2; np++) {       // n16 pairs
                uint32_t n = (uint32_t)(warp_n * 32 + np * 16) + b_row;
                uint32_t bd = sb + n * GSTR + cbB;
                uint32_t h0, h1, h2, h3, l0, l1, l2, l3;
                ldsm4(h0, h1, h2, h3, bd + OB_HI);
                ldsm4(l0, l1, l2, l3, bd + OB_LO);
                uint32_t bh0[2] = {h0, h1}, bh1[2] = {h2, h3};
                uint32_t bl0[2] = {l0, l1}, bl1[2] = {l2, l3};
#pragma unroll
                for (int mi = 0; mi < 4; mi++) {
                    mma_bf16(acc[mi][np * 2],     ah[mi], bh0);
                    mma_bf16(acc[mi][np * 2],     ah[mi], bl0);
                    mma_bf16(acc[mi][np * 2],     al[mi], bh0);
                    mma_bf16(acc[mi][np * 2 + 1], ah[mi], bh1);
                    mma_bf16(acc[mi][np * 2 + 1], ah[mi], bl1);
                    mma_bf16(acc[mi][np * 2 + 1], al[mi], bh1);
                }
            }
        }
    }

    // epilogue
#pragma unroll
    for (int mi = 0; mi < 4; mi++) {
        int r = row0 + warp_m * 64 + mi * 16 + g;       // rows r, r+8
#pragma unroll
        for (int ni = 0; ni < 4; ni++) {
            int col = col0 + warp_n * 32 + ni * 8 + tig * 2;
            if (OutF) {
                *(float2*)&OutF[(size_t)r * HIDDEN + col] =
                    make_float2(acc[mi][ni][0], acc[mi][ni][1]);
                *(float2*)&OutF[(size_t)(r + 8) * HIDDEN + col] =
                    make_float2(acc[mi][ni][2], acc[mi][ni][3]);
            } else {
                int h = col >> 6, d = col & 63;
                int b0 = r >> 11, s0 = r & 2047;
                int b1 = (r + 8) >> 11, s1 = (r + 8) & 2047;
                size_t i0 = (((size_t)(b0 * HEADS + h)) * SEQ + s0) * HDIM + d;
                size_t i1 = (((size_t)(b1 * HEADS + h)) * SEQ + s1) * HDIM + d;
                uint32_t hi, lo;
                hilo2(acc[mi][ni][0], acc[mi][ni][1], hi, lo);
                *(uint32_t*)&OutHi[i0] = hi;  *(uint32_t*)&OutLo[i0] = lo;
                hilo2(acc[mi][ni][2], acc[mi][ni][3], hi, lo);
                *(uint32_t*)&OutHi[i1] = hi;  *(uint32_t*)&OutLo[i1] = lo;
            }
        }
    }
}

__global__ __launch_bounds__(256) void gemm_qkv() {
    const int z = blockIdx.z;
    const size_t zoff = (size_t)z * HIDDEN * HIDDEN;
    bf16* oh = (z == 0) ? g_qhi : (z == 1) ? g_khi : g_vhi;
    bf16* ol = (z == 0) ? g_qlo : (z == 1) ? g_klo : g_vlo;
    gemm_body(s_xhi, s_xlo, s_whi + zoff, s_wlo + zoff, oh, ol, nullptr);
}
__global__ __launch_bounds__(256) void gemm_out(float* __restrict__ out) {
    const size_t zoff = (size_t)3 * HIDDEN * HIDDEN;
    gemm_body(g_ohi, g_olo, s_whi + zoff, s_wlo + zoff, nullptr, nullptr, out);
}

// ---------------------------------------------------------------------------
// Flash attention, tensor-core split-bf16. Br=128, Bc=64, 8 warps.
// ---------------------------------------------------------------------------
#define FQ_B   (128 * 128)              // 16384 bytes per Q matrix
#define FKV_B  (64 * 128)               // 8192 per KV matrix
#define OQH    0
#define OQL    FQ_B
#define OKV    (2 * FQ_B)
#define FSTAGE_B (4 * FKV_B)            // KH,KL,VH,VL = 32768
#define FSMEM  (2 * FQ_B + 2 * FSTAGE_B) // 98304

// 128B rows, XOR swizzle on the 16B column within the row
__device__ __forceinline__ uint32_t fsw(uint32_t r, uint32_t cb) {
    return r * 128u + ((((cb >> 4) ^ r) & 7u) << 4);
}

__global__ __launch_bounds__(256) void flash_tc()
{
    extern __shared__ __align__(16) char fsm[];
    const uint32_t sb = smem_u32(fsm);

    const int tid = threadIdx.x;
    const int lane = tid & 31;
    const int wid = tid >> 5;
    const int g = lane >> 2, tig = lane & 3;
    const int bh = blockIdx.y;
    const int q0 = blockIdx.x * 128;
    const size_t bho = (size_t)bh * SEQ * HDIM;

    // ---- prologue loads: G0 = Q + KV0, G1 = KV1 ----
    {
        const bf16* qsrc[2] = {g_qhi + bho, g_qlo + bho};
#pragma unroll
        for (int m = 0; m < 2; m++)
#pragma unroll
            for (int i = 0; i < 4; i++) {
                int idx = tid + i * 256;           // 1024 chunks
                int r = idx >> 3, c = idx & 7;
                cp16(sb + (m ? OQL : OQH) + fsw(r, c * 16),
                     qsrc[m] + (size_t)(q0 + r) * HDIM + c * 8);
            }
    }
    auto load_kv = [&](int t, int buf) {
        const int j0 = t * 64;
        const bf16* src[4] = {g_khi + bho, g_klo + bho, g_vhi + bho, g_vlo + bho};
        uint32_t base = sb + OKV + buf * FSTAGE_B;
#pragma unroll
        for (int m = 0; m < 4; m++)
#pragma unroll
            for (int i = 0; i < 2; i++) {
                int idx = tid + i * 256;           // 512 chunks per matrix
                int r = idx >> 3, c = idx & 7;
                cp16(base + m * FKV_B + fsw(r, c * 16),
                     src[m] + (size_t)(j0 + r) * HDIM + c * 8);
            }
    };
    load_kv(0, 0);
    CP_COMMIT();
    load_kv(1, 1);
    CP_COMMIT();

    float m0 = -1e30f, m1 = -1e30f, l0 = 0.f, l1 = 0.f;
    float o[8][4];
#pragma unroll
    for (int dt = 0; dt < 8; dt++)
#pragma unroll
        for (int e = 0; e < 4; e++) o[dt][e] = 0.f;
    uint32_t qh[4][4], ql[4][4];

    const uint32_t a_row = (uint32_t)(((lane >> 3) & 1) * 8 + (lane & 7));
    const uint32_t a_cb  = (uint32_t)((lane >> 4) * 16);
    const uint32_t b_row = (uint32_t)((lane >> 4) * 8 + (lane & 7));
    const uint32_t b_cb  = (uint32_t)(((lane >> 3) & 1) * 16);

    const int nt = 2 * blockIdx.x + 2;
    for (int t = 0; t < nt; t++) {
        CP_WAIT1();
        __syncthreads();
        if (t == 0) {
            // Q fragments, kept in registers for the whole block
#pragma unroll
            for (int ks = 0; ks < 4; ks++) {
                uint32_t r = (uint32_t)(wid * 16) + a_row;
                uint32_t cb = (uint32_t)(ks * 32) + a_cb;
                ldsm4(qh[ks][0], qh[ks][1], qh[ks][2], qh[ks][3], sb + OQH + fsw(r, cb));
                ldsm4(ql[ks][0], ql[ks][1], ql[ks][2], ql[ks][3], sb + OQL + fsw(r, cb));
            }
        }
        const uint32_t kvb = sb + OKV + (t & 1) * FSTAGE_B;

        // ---- S = Q K^T ----
        float s[8][4];
#pragma unroll
        for (int j = 0; j < 8; j++)
#pragma unroll
            for (int e = 0; e < 4; e++) s[j][e] = 0.f;
#pragma unroll
        for (int ks = 0; ks < 4; ks++) {
            const uint32_t cb = (uint32_t)(ks * 32) + b_cb;
#pragma unroll
            for (int np = 0; np < 4; np++) {
                uint32_t n = (uint32_t)(np * 16) + b_row;
                uint32_t h0, h1, h2, h3, l0r, l1r, l2r, l3r;
                ldsm4(h0, h1, h2, h3, kvb + 0 * FKV_B + fsw(n, cb));
                ldsm4(l0r, l1r, l2r, l3r, kvb + 1 * FKV_B + fsw(n, cb));
                uint32_t bh0[2] = {h0, h1}, bh1[2] = {h2, h3};
                uint32_t bl0[2] = {l0r, l1r}, bl1[2] = {l2r, l3r};
                mma_bf16(s[np * 2],     qh[ks], bh0);
                mma_bf16(s[np * 2],     qh[ks], bl0);
                mma_bf16(s[np * 2],     ql[ks], bh0);
                mma_bf16(s[np * 2 + 1], qh[ks], bh1);
                mma_bf16(s[np * 2 + 1], qh[ks], bl1);
                mma_bf16(s[np * 2 + 1], ql[ks], bh1);
            }
        }

        // ---- scale + causal mask ----
        const bool masked = (t >= 2 * (int)blockIdx.x);
        const int j0 = t * 64;
        const int r0 = q0 + wid * 16 + g;
#pragma unroll
        for (int j = 0; j < 8; j++) {
#pragma unroll
            for (int e = 0; e < 4; e++) {
                float v = s[j][e] * QK_SCALE;
                if (masked) {
                    int col = j0 + j * 8 + tig * 2 + (e & 1);
                    int row = r0 + ((e >> 1) * 8);
                    if (col > row) v = -1e9f;
                }
                s[j][e] = v;
            }
        }

        // ---- online softmax (rows g and g+8) ----
        float mx0 = -1e30f, mx1 = -1e30f;
#pragma unroll
        for (int j = 0; j < 8; j++) {
            mx0 = fmaxf(mx0, fmaxf(s[j][0], s[j][1]));
            mx1 = fmaxf(mx1, fmaxf(s[j][2], s[j][3]));
        }
        mx0 = fmaxf(mx0, __shfl_xor_sync(0xffffffffu, mx0, 1));
        mx0 = fmaxf(mx0, __shfl_xor_sync(0xffffffffu, mx0, 2));
        mx1 = fmaxf(mx1, __shfl_xor_sync(0xffffffffu, mx1, 1));
        mx1 = fmaxf(mx1, __shfl_xor_sync(0xffffffffu, mx1, 2));
        float mn0 = fmaxf(m0, mx0), mn1 = fmaxf(m1, mx1);
        float al0 = __expf(m0 - mn0), al1 = __expf(m1 - mn1);
        float sum0 = 0.f, sum1 = 0.f;
#pragma unroll
        for (int j = 0; j < 8; j++) {
            s[j][0] = __expf(s[j][0] - mn0); sum0 += s[j][0];
            s[j][1] = __expf(s[j][1] - mn0); sum0 += s[j][1];
            s[j][2] = __expf(s[j][2] - mn1); sum1 += s[j][2];
            s[j][3] = __expf(s[j][3] - mn1); sum1 += s[j][3];
        }
        sum0 += __shfl_xor_sync(0xffffffffu, sum0, 1);
        sum0 += __shfl_xor_sync(0xffffffffu, sum0, 2);
        sum1 += __shfl_xor_sync(0xffffffffu, sum1, 1);
        sum1 += __shfl_xor_sync(0xffffffffu, sum1, 2);
        l0 = l0 * al0 + sum0;  m0 = mn0;
        l1 = l1 * al1 + sum1;  m1 = mn1;
#pragma unroll
        for (int dt = 0; dt < 8; dt++) {
            o[dt][0] *= al0; o[dt][1] *= al0;
            o[dt][2] *= al1; o[dt][3] *= al1;
        }

        // ---- O += P V ----
#pragma unroll
        for (int kp = 0; kp < 4; kp++) {
            uint32_t ph[4], pl[4];
            hilo2(s[2 * kp][0],     s[2 * kp][1],     ph[0], pl[0]);
            hilo2(s[2 * kp][2],     s[2 * kp][3],     ph[1], pl[1]);
            hilo2(s[2 * kp + 1][0], s[2 * kp + 1][1], ph[2], pl[2]);
            hilo2(s[2 * kp + 1][2], s[2 * kp + 1][3], ph[3], pl[3]);
            uint32_t kr = (uint32_t)(kp * 16) + a_row;     // kv row within tile
#pragma unroll
            for (int np = 0; np < 4; np++) {
                uint32_t cb = (uint32_t)(np * 32) + a_cb;  // d col bytes
                uint32_t v0, v1, v2, v3, w0, w1, w2, w3;
                ldsm4t(v0, v1, v2, v3, kvb + 2 * FKV_B + fsw(kr, cb));
                ldsm4t(w0, w1, w2, w3, kvb + 3 * FKV_B + fsw(kr, cb));
                uint32_t bh0[2] = {v0, v1}, bh1[2] = {v2, v3};
                uint32_t bl0[2] = {w0, w1}, bl1[2] = {w2, w3};
                mma_bf16(o[np * 2],     ph, bh0);
                mma_bf16(o[np * 2],     ph, bl0);
                mma_bf16(o[np * 2],     pl, bh0);
                mma_bf16(o[np * 2 + 1], ph, bh1);
                mma_bf16(o[np * 2 + 1], ph, bl1);
                mma_bf16(o[np * 2 + 1], pl, bh1);
            }
        }

        __syncthreads();
        if (t + 2 < nt) load_kv(t + 2, t & 1);
        CP_COMMIT();
    }

    // ---- epilogue: O/l -> bf16 hi/lo at [b][s][h*64+d] ----
    const int b = bh >> 4, h = bh & 15;
    const int s0 = q0 + wid * 16 + g;
    const float i0 = 1.f / l0, i1 = 1.f / l1;
#pragma unroll
    for (int dt = 0; dt < 8; dt++) {
        int d = dt * 8 + tig * 2;
        size_t base0 = ((size_t)(b * SEQ) + s0) * HIDDEN + h * HDIM + d;
        size_t base1 = base0 + (size_t)8 * HIDDEN;
        uint32_t hi, lo;
        hilo2(o[dt][0] * i0, o[dt][1] * i0, hi, lo);
        *(uint32_t*)&g_ohi[base0] = hi;  *(uint32_t*)&g_olo[base0] = lo;
        hilo2(o[dt][2] * i1, o[dt][3] * i1, hi, lo);
        *(uint32_t*)&g_ohi[base1] = hi;  *(uint32_t*)&g_olo[base1] = lo;
    }
}

// ---------------------------------------------------------------------------
// Launch
// ---------------------------------------------------------------------------
extern "C" void kernel_launch(void* const* d_in, const int* in_sizes, int n_in,
                              void* d_out, int out_size)
{
    const float* X  = (const float*)d_in[0];
    // d_in[1] = attention_mask (exact causal; applied analytically)
    const float* Wq = (const float*)d_in[2];
    const float* Wk = (const float*)d_in[3];
    const float* Wv = (const float*)d_in[4];
    const float* Wo = (const float*)d_in[5];
    float* out = (float*)d_out;

    cudaFuncSetAttribute(gemm_qkv, cudaFuncAttributeMaxDynamicSharedMemorySize, GSMEM);
    cudaFuncSetAttribute(gemm_out, cudaFuncAttributeMaxDynamicSharedMemorySize, GSMEM);
    cudaFuncSetAttribute(flash_tc, cudaFuncAttributeMaxDynamicSharedMemorySize, FSMEM);

    convert_x<<<NTOK * HIDDEN / 1024, 256>>>(X);
    transpose_w<<<dim3(32, 32, 4), dim3(32, 8)>>>(Wq, Wk, Wv, Wo);

    gemm_qkv<<<dim3(HIDDEN / 128, NTOK / 128, 3), 256, GSMEM>>>();

    flash_tc<<<dim3(SEQ / 128, BATCH * HEADS), 256, FSMEM>>>();

    gemm_out<<<dim3(HIDDEN / 128, NTOK / 128), 256, GSMEM>>>(out);
}

// round 7
// speedup vs baseline: 2.6413x; 1.0148x over previous
#include <cuda_runtime.h>
#include <cuda_bf16.h>
#include <cstdint>

#define BATCH   2
#define SEQ     2048
#define HIDDEN  1024
#define HEADS   16
#define HDIM    64
#define NTOK    (BATCH * SEQ)          // 4096
#define QK_SCALE 0.125f

typedef __nv_bfloat16 bf16;

// ---------------------------------------------------------------------------
// Device scratch (no cudaMalloc allowed)
// ---------------------------------------------------------------------------
__device__ bf16 s_xhi[NTOK * HIDDEN];               // X split-bf16
__device__ bf16 s_xlo[NTOK * HIDDEN];
__device__ bf16 s_whi[4 * HIDDEN * HIDDEN];         // W^T split-bf16 (q,k,v,o)
__device__ bf16 s_wlo[4 * HIDDEN * HIDDEN];
__device__ bf16 g_qhi[BATCH * HEADS * SEQ * HDIM];  // [B,H,S,D]
__device__ bf16 g_qlo[BATCH * HEADS * SEQ * HDIM];
__device__ bf16 g_khi[BATCH * HEADS * SEQ * HDIM];
__device__ bf16 g_klo[BATCH * HEADS * SEQ * HDIM];
__device__ bf16 g_vhi[BATCH * HEADS * SEQ * HDIM];
__device__ bf16 g_vlo[BATCH * HEADS * SEQ * HDIM];
__device__ bf16 g_ohi[NTOK * HIDDEN];               // attention out [B,S,H*D]
__device__ bf16 g_olo[NTOK * HIDDEN];

// ---------------------------------------------------------------------------
// PTX helpers
// ---------------------------------------------------------------------------
__device__ __forceinline__ uint32_t smem_u32(const void* p) {
    uint32_t a;
    asm("{ .reg .u64 t; cvta.to.shared.u64 t, %1; cvt.u32.u64 %0, t; }" : "=r"(a) : "l"(p));
    return a;
}
__device__ __forceinline__ void cp16(uint32_t s, const void* g) {
    asm volatile("cp.async.cg.shared.global [%0], [%1], 16;" :: "r"(s), "l"(g) : "memory");
}
#define CP_COMMIT() asm volatile("cp.async.commit_group;" ::: "memory")
#define CP_WAIT1()  asm volatile("cp.async.wait_group 1;" ::: "memory")

__device__ __forceinline__ void ldsm4(uint32_t& r0, uint32_t& r1, uint32_t& r2, uint32_t& r3, uint32_t a) {
    asm volatile("ldmatrix.sync.aligned.m8n8.x4.shared.b16 {%0,%1,%2,%3}, [%4];"
                 : "=r"(r0), "=r"(r1), "=r"(r2), "=r"(r3) : "r"(a));
}
__device__ __forceinline__ void ldsm4t(uint32_t& r0, uint32_t& r1, uint32_t& r2, uint32_t& r3, uint32_t a) {
    asm volatile("ldmatrix.sync.aligned.m8n8.x4.trans.shared.b16 {%0,%1,%2,%3}, [%4];"
                 : "=r"(r0), "=r"(r1), "=r"(r2), "=r"(r3) : "r"(a));
}
__device__ __forceinline__ void mma_bf16(float d[4], const uint32_t a[4], const uint32_t b[2]) {
    asm volatile(
        "mma.sync.aligned.m16n8k16.row.col.f32.bf16.bf16.f32 "
        "{%0,%1,%2,%3}, {%4,%5,%6,%7}, {%8,%9}, {%0,%1,%2,%3};"
        : "+f"(d[0]), "+f"(d[1]), "+f"(d[2]), "+f"(d[3])
        : "r"(a[0]), "r"(a[1]), "r"(a[2]), "r"(a[3]), "r"(b[0]), "r"(b[1]));
}
// split x,y into packed bf16 hi pair + lo pair
__device__ __forceinline__ void hilo2(float x, float y, uint32_t& hi, uint32_t& lo) {
    __nv_bfloat16 hx = __float2bfloat16_rn(x), hy = __float2bfloat16_rn(y);
    float rx = x - __bfloat162float(hx), ry = y - __bfloat162float(hy);
    __nv_bfloat16 lx = __float2bfloat16_rn(rx), ly = __float2bfloat16_rn(ry);
    hi = (uint32_t)__bfloat16_as_ushort(hx) | ((uint32_t)__bfloat16_as_ushort(hy) << 16);
    lo = (uint32_t)__bfloat16_as_ushort(lx) | ((uint32_t)__bfloat16_as_ushort(ly) << 16);
}

// ---------------------------------------------------------------------------
// Pre-convert kernels
// ---------------------------------------------------------------------------
__global__ __launch_bounds__(256) void convert_x(const float* __restrict__ X) {
    size_t i4 = ((size_t)blockIdx.x * 256 + threadIdx.x) * 4;
    float4 v = *(const float4*)&X[i4];
    uint32_t h0, l0, h1, l1;
    hilo2(v.x, v.y, h0, l0);
    hilo2(v.z, v.w, h1, l1);
    *(uint32_t*)&s_xhi[i4]     = h0;  *(uint32_t*)&s_xhi[i4 + 2] = h1;
    *(uint32_t*)&s_xlo[i4]     = l0;  *(uint32_t*)&s_xlo[i4 + 2] = l1;
}

// W [k][n] -> Wt [n][k] split-bf16, 32x32 tiles
__global__ __launch_bounds__(256) void transpose_w(
    const float* __restrict__ w0, const float* __restrict__ w1,
    const float* __restrict__ w2, const float* __restrict__ w3)
{
    __shared__ float t[32][33];
    const int z = blockIdx.z;
    const float* W = (z == 0) ? w0 : (z == 1) ? w1 : (z == 2) ? w2 : w3;
    const size_t zoff = (size_t)z * HIDDEN * HIDDEN;
    const int n0 = blockIdx.x * 32, k0 = blockIdx.y * 32;
    const int tx = threadIdx.x, ty = threadIdx.y;   // 32 x 8
#pragma unroll
    for (int i = 0; i < 4; i++)
        t[ty + i * 8][tx] = W[(size_t)(k0 + ty + i * 8) * HIDDEN + n0 + tx];
    __syncthreads();
#pragma unroll
    for (int i = 0; i < 4; i++) {
        int nr = ty + i * 8;
        float v = t[tx][nr];
        bf16 h = __float2bfloat16_rn(v);
        bf16 l = __float2bfloat16_rn(v - __bfloat162float(h));
        s_whi[zoff + (size_t)(n0 + nr) * HIDDEN + k0 + tx] = h;
        s_wlo[zoff + (size_t)(n0 + nr) * HIDDEN + k0 + tx] = l;
    }
}

// ---------------------------------------------------------------------------
// Split-bf16 GEMM: C[4096x1024] = A @ Wt^T ; A,Wt row-major bf16 hi/lo.
// Block 256x128xBK32, 3-stage cp.async, ldmatrix, 8 warps (warp tile 64x64).
// ---------------------------------------------------------------------------
#define GBK     32
#define GKITERS (HIDDEN / GBK)          // 32
#define GSTR    80                      // bytes per smem row (40 bf16, pad)
#define OA_HI   0
#define OA_LO   (256 * GSTR)            // 20480
#define OB_HI   (2 * 256 * GSTR)        // 40960
#define OB_LO   (OB_HI + 128 * GSTR)    // 51200
#define GSTAGE_B (OB_HI + 2 * 128 * GSTR)  // 61440
#define GNSTAGE 3
#define GSMEM   (GNSTAGE * GSTAGE_B)    // 184320

__device__ __forceinline__ void gemm_load_stage(
    uint32_t sb, const bf16* __restrict__ Ahi, const bf16* __restrict__ Alo,
    const bf16* __restrict__ Bhi, const bf16* __restrict__ Blo,
    int row0, int col0, int kc, int tid)
{
    const int k0 = kc * GBK;
#pragma unroll
    for (int i = 0; i < 4; i++) {
        int idx = tid + i * 256;        // 1024 chunks per matrix (256 rows x 4)
        int r = idx >> 2, c = idx & 3;
        uint32_t so = (uint32_t)(r * GSTR + c * 16);
        size_t ga = (size_t)(row0 + r) * HIDDEN + k0 + c * 8;
        cp16(sb + OA_HI + so, &Ahi[ga]);
        cp16(sb + OA_LO + so, &Alo[ga]);
    }
#pragma unroll
    for (int i = 0; i < 2; i++) {
        int idx = tid + i * 256;        // 512 chunks per matrix (128 rows x 4)
        int r = idx >> 2, c = idx & 3;
        uint32_t so = (uint32_t)(r * GSTR + c * 16);
        size_t gb = (size_t)(col0 + r) * HIDDEN + k0 + c * 8;
        cp16(sb + OB_HI + so, &Bhi[gb]);
        cp16(sb + OB_LO + so, &Blo[gb]);
    }
}

__device__ __forceinline__ void gemm_body(
    const bf16* __restrict__ Ahi, const bf16* __restrict__ Alo,
    const bf16* __restrict__ Bhi, const bf16* __restrict__ Blo,
    bf16* __restrict__ OutHi, bf16* __restrict__ OutLo,   // mode qkv (permuted)
    float* __restrict__ OutF)                             // mode fp32 row-major
{
    extern __shared__ __align__(16) char gsm[];
    const uint32_t sb0 = smem_u32(gsm);

    const int tid = threadIdx.x;
    const int lane = tid & 31;
    const int wid = tid >> 5;
    const int g = lane >> 2, tig = lane & 3;
    const int warp_m = wid >> 1;       // 0..3 (64 rows each)
    const int warp_n = wid & 1;        // 0..1 (64 cols each)
    const int row0 = blockIdx.y * 256;
    const int col0 = blockIdx.x * 128;

    float acc[4][8][4];
#pragma unroll
    for (int mi = 0; mi < 4; mi++)
#pragma unroll
        for (int nj = 0; nj < 8; nj++)
#pragma unroll
            for (int e = 0; e < 4; e++) acc[mi][nj][e] = 0.f;

    // prologue: stages 0..1
    for (int p = 0; p < 2; p++) {
        gemm_load_stage(sb0 + p * GSTAGE_B, Ahi, Alo, Bhi, Blo, row0, col0, p, tid);
        CP_COMMIT();
    }

    const uint32_t a_row = (uint32_t)(((lane >> 3) & 1) * 8 + (lane & 7));
    const uint32_t a_cb  = (uint32_t)((lane >> 4) * 16);
    const uint32_t b_row = (uint32_t)((lane >> 4) * 8 + (lane & 7));
    const uint32_t b_cb  = (uint32_t)(((lane >> 3) & 1) * 16);

    for (int kc = 0; kc < GKITERS; kc++) {
        CP_WAIT1();
        __syncthreads();
        if (kc + 2 < GKITERS)
            gemm_load_stage(sb0 + ((kc + 2) % 3) * GSTAGE_B, Ahi, Alo, Bhi, Blo,
                            row0, col0, kc + 2, tid);
        CP_COMMIT();

        const uint32_t sb = sb0 + (kc % 3) * GSTAGE_B;
#pragma unroll
        for (int ks = 0; ks < 2; ks++) {           // two k16 slices
            const uint32_t cbA = (uint32_t)(ks * 32) + a_cb;
            const uint32_t cbB = (uint32_t)(ks * 32) + b_cb;
            uint32_t ah[4][4], al[4][4];
#pragma unroll
            for (int mi = 0; mi < 4; mi++) {
                uint32_t r = (uint32_t)(warp_m * 64 + mi * 16) + a_row;
                uint32_t ad = sb + r * GSTR + cbA;
                ldsm4(ah[mi][0], ah[mi][1], ah[mi][2], ah[mi][3], ad + OA_HI);
                ldsm4(al[mi][0], al[mi][1], al[mi][2], al[mi][3], ad + OA_LO);
            }
#pragma unroll
            for (int np = 0; np < 4; np++) {       // n16 pairs
                uint32_t n = (uint32_t)(warp_n * 64 + np * 16) + b_row;
                uint32_t bd = sb + n * GSTR + cbB;
                uint32_t h0, h1, h2, h3, l0, l1, l2, l3;
                ldsm4(h0, h1, h2, h3, bd + OB_HI);
                ldsm4(l0, l1, l2, l3, bd + OB_LO);
                uint32_t bh0[2] = {h0, h1}, bh1[2] = {h2, h3};
                uint32_t bl0[2] = {l0, l1}, bl1[2] = {l2, l3};
#pragma unroll
                for (int mi = 0; mi < 4; mi++) {
                    mma_bf16(acc[mi][np * 2],     ah[mi], bh0);
                    mma_bf16(acc[mi][np * 2],     ah[mi], bl0);
                    mma_bf16(acc[mi][np * 2],     al[mi], bh0);
                    mma_bf16(acc[mi][np * 2 + 1], ah[mi], bh1);
                    mma_bf16(acc[mi][np * 2 + 1], ah[mi], bl1);
                    mma_bf16(acc[mi][np * 2 + 1], al[mi], bh1);
                }
            }
        }
    }

    // epilogue
#pragma unroll
    for (int mi = 0; mi < 4; mi++) {
        int r = row0 + warp_m * 64 + mi * 16 + g;       // rows r, r+8
#pragma unroll
        for (int nj = 0; nj < 8; nj++) {
            int col = col0 + warp_n * 64 + nj * 8 + tig * 2;
            if (OutF) {
                *(float2*)&OutF[(size_t)r * HIDDEN + col] =
                    make_float2(acc[mi][nj][0], acc[mi][nj][1]);
                *(float2*)&OutF[(size_t)(r + 8) * HIDDEN + col] =
                    make_float2(acc[mi][nj][2], acc[mi][nj][3]);
            } else {
                int h = col >> 6, d = col & 63;
                int b0 = r >> 11, s0 = r & 2047;
                int b1 = (r + 8) >> 11, s1 = (r + 8) & 2047;
                size_t i0 = (((size_t)(b0 * HEADS + h)) * SEQ + s0) * HDIM + d;
                size_t i1 = (((size_t)(b1 * HEADS + h)) * SEQ + s1) * HDIM + d;
                uint32_t hi, lo;
                hilo2(acc[mi][nj][0], acc[mi][nj][1], hi, lo);
                *(uint32_t*)&OutHi[i0] = hi;  *(uint32_t*)&OutLo[i0] = lo;
                hilo2(acc[mi][nj][2], acc[mi][nj][3], hi, lo);
                *(uint32_t*)&OutHi[i1] = hi;  *(uint32_t*)&OutLo[i1] = lo;
            }
        }
    }
}

__global__ __launch_bounds__(256) void gemm_qkv() {
    const int z = blockIdx.z;
    const size_t zoff = (size_t)z * HIDDEN * HIDDEN;
    bf16* oh = (z == 0) ? g_qhi : (z == 1) ? g_khi : g_vhi;
    bf16* ol = (z == 0) ? g_qlo : (z == 1) ? g_klo : g_vlo;
    gemm_body(s_xhi, s_xlo, s_whi + zoff, s_wlo + zoff, oh, ol, nullptr);
}
__global__ __launch_bounds__(256) void gemm_out(float* __restrict__ out) {
    const size_t zoff = (size_t)3 * HIDDEN * HIDDEN;
    gemm_body(g_ohi, g_olo, s_whi + zoff, s_wlo + zoff, nullptr, nullptr, out);
}

// ---------------------------------------------------------------------------
// Flash attention, tensor-core split-bf16. Br=128, Bc=64, 8 warps, 2 CTAs/SM.
// ---------------------------------------------------------------------------
#define FQ_B   (128 * 128)              // 16384 bytes per Q matrix
#define FKV_B  (64 * 128)               // 8192 per KV matrix
#define OQH    0
#define OQL    FQ_B
#define OKV    (2 * FQ_B)
#define FSTAGE_B (4 * FKV_B)            // KH,KL,VH,VL = 32768
#define FSMEM  (2 * FQ_B + 2 * FSTAGE_B) // 98304 (x2 CTAs = 192K <= 228K)

// 128B rows, XOR swizzle on the 16B column within the row
__device__ __forceinline__ uint32_t fsw(uint32_t r, uint32_t cb) {
    return r * 128u + ((((cb >> 4) ^ r) & 7u) << 4);
}

__global__ __launch_bounds__(256, 2) void flash_tc()
{
    extern __shared__ __align__(16) char fsm[];
    const uint32_t sb = smem_u32(fsm);

    const int tid = threadIdx.x;
    const int lane = tid & 31;
    const int wid = tid >> 5;
    const int g = lane >> 2, tig = lane & 3;
    const int bh = blockIdx.y;
    const int q0 = blockIdx.x * 128;
    const size_t bho = (size_t)bh * SEQ * HDIM;

    // ---- prologue loads: G0 = Q + KV0, G1 = KV1 ----
    {
        const bf16* qsrc[2] = {g_qhi + bho, g_qlo + bho};
#pragma unroll
        for (int m = 0; m < 2; m++)
#pragma unroll
            for (int i = 0; i < 4; i++) {
                int idx = tid + i * 256;           // 1024 chunks
                int r = idx >> 3, c = idx & 7;
                cp16(sb + (m ? OQL : OQH) + fsw(r, c * 16),
                     qsrc[m] + (size_t)(q0 + r) * HDIM + c * 8);
            }
    }
    auto load_kv = [&](int t, int buf) {
        const int j0 = t * 64;
        const bf16* src[4] = {g_khi + bho, g_klo + bho, g_vhi + bho, g_vlo + bho};
        uint32_t base = sb + OKV + buf * FSTAGE_B;
#pragma unroll
        for (int m = 0; m < 4; m++)
#pragma unroll
            for (int i = 0; i < 2; i++) {
                int idx = tid + i * 256;           // 512 chunks per matrix
                int r = idx >> 3, c = idx & 7;
                cp16(base + m * FKV_B + fsw(r, c * 16),
                     src[m] + (size_t)(j0 + r) * HDIM + c * 8);
            }
    };
    load_kv(0, 0);
    CP_COMMIT();
    load_kv(1, 1);
    CP_COMMIT();

    float m0 = -1e30f, m1 = -1e30f, l0 = 0.f, l1 = 0.f;
    float o[8][4];
#pragma unroll
    for (int dt = 0; dt < 8; dt++)
#pragma unroll
        for (int e = 0; e < 4; e++) o[dt][e] = 0.f;

    const uint32_t a_row = (uint32_t)(((lane >> 3) & 1) * 8 + (lane & 7));
    const uint32_t a_cb  = (uint32_t)((lane >> 4) * 16);
    const uint32_t b_row = (uint32_t)((lane >> 4) * 8 + (lane & 7));
    const uint32_t b_cb  = (uint32_t)(((lane >> 3) & 1) * 16);
    const uint32_t q_row = (uint32_t)(wid * 16) + a_row;

    const int nt = 2 * blockIdx.x + 2;
    for (int t = 0; t < nt; t++) {
        CP_WAIT1();
        __syncthreads();
        const uint32_t kvb = sb + OKV + (t & 1) * FSTAGE_B;

        // ---- S = Q K^T (Q frags reloaded per k16 slice; low reg pressure) ----
        float s[8][4];
#pragma unroll
        for (int j = 0; j < 8; j++)
#pragma unroll
            for (int e = 0; e < 4; e++) s[j][e] = 0.f;
#pragma unroll
        for (int ks = 0; ks < 4; ks++) {
            const uint32_t cbq = (uint32_t)(ks * 32) + a_cb;
            uint32_t qh[4], ql[4];
            ldsm4(qh[0], qh[1], qh[2], qh[3], sb + OQH + fsw(q_row, cbq));
            ldsm4(ql[0], ql[1], ql[2], ql[3], sb + OQL + fsw(q_row, cbq));
            const uint32_t cb = (uint32_t)(ks * 32) + b_cb;
#pragma unroll
            for (int np = 0; np < 4; np++) {
                uint32_t n = (uint32_t)(np * 16) + b_row;
                uint32_t h0, h1, h2, h3, l0r, l1r, l2r, l3r;
                ldsm4(h0, h1, h2, h3, kvb + 0 * FKV_B + fsw(n, cb));
                ldsm4(l0r, l1r, l2r, l3r, kvb + 1 * FKV_B + fsw(n, cb));
                uint32_t bh0[2] = {h0, h1}, bh1[2] = {h2, h3};
                uint32_t bl0[2] = {l0r, l1r}, bl1[2] = {l2r, l3r};
                mma_bf16(s[np * 2],     qh, bh0);
                mma_bf16(s[np * 2],     qh, bl0);
                mma_bf16(s[np * 2],     ql, bh0);
                mma_bf16(s[np * 2 + 1], qh, bh1);
                mma_bf16(s[np * 2 + 1], qh, bl1);
                mma_bf16(s[np * 2 + 1], ql, bh1);
            }
        }

        // ---- scale + causal mask ----
        const bool masked = (t >= 2 * (int)blockIdx.x);
        const int j0 = t * 64;
        const int r0 = q0 + wid * 16 + g;
#pragma unroll
        for (int j = 0; j < 8; j++) {
#pragma unroll
            for (int e = 0; e < 4; e++) {
                float v = s[j][e] * QK_SCALE;
                if (masked) {
                    int col = j0 + j * 8 + tig * 2 + (e & 1);
                    int row = r0 + ((e >> 1) * 8);
                    if (col > row) v = -1e9f;
                }
                s[j][e] = v;
            }
        }

        // ---- online softmax (rows g and g+8) ----
        float mx0 = -1e30f, mx1 = -1e30f;
#pragma unroll
        for (int j = 0; j < 8; j++) {
            mx0 = fmaxf(mx0, fmaxf(s[j][0], s[j][1]));
            mx1 = fmaxf(mx1, fmaxf(s[j][2], s[j][3]));
        }
        mx0 = fmaxf(mx0, __shfl_xor_sync(0xffffffffu, mx0, 1));
        mx0 = fmaxf(mx0, __shfl_xor_sync(0xffffffffu, mx0, 2));
        mx1 = fmaxf(mx1, __shfl_xor_sync(0xffffffffu, mx1, 1));
        mx1 = fmaxf(mx1, __shfl_xor_sync(0xffffffffu, mx1, 2));
        float mn0 = fmaxf(m0, mx0), mn1 = fmaxf(m1, mx1);
        float al0 = __expf(m0 - mn0), al1 = __expf(m1 - mn1);
        float sum0 = 0.f, sum1 = 0.f;
#pragma unroll
        for (int j = 0; j < 8; j++) {
            s[j][0] = __expf(s[j][0] - mn0); sum0 += s[j][0];
            s[j][1] = __expf(s[j][1] - mn0); sum0 += s[j][1];
            s[j][2] = __expf(s[j][2] - mn1); sum1 += s[j][2];
            s[j][3] = __expf(s[j][3] - mn1); sum1 += s[j][3];
        }
        sum0 += __shfl_xor_sync(0xffffffffu, sum0, 1);
        sum0 += __shfl_xor_sync(0xffffffffu, sum0, 2);
        sum1 += __shfl_xor_sync(0xffffffffu, sum1, 1);
        sum1 += __shfl_xor_sync(0xffffffffu, sum1, 2);
        l0 = l0 * al0 + sum0;  m0 = mn0;
        l1 = l1 * al1 + sum1;  m1 = mn1;
#pragma unroll
        for (int dt = 0; dt < 8; dt++) {
            o[dt][0] *= al0; o[dt][1] *= al0;
            o[dt][2] *= al1; o[dt][3] *= al1;
        }

        // ---- O += P V ----
#pragma unroll
        for (int kp = 0; kp < 4; kp++) {
            uint32_t ph[4], pl[4];
            hilo2(s[2 * kp][0],     s[2 * kp][1],     ph[0], pl[0]);
            hilo2(s[2 * kp][2],     s[2 * kp][3],     ph[1], pl[1]);
            hilo2(s[2 * kp + 1][0], s[2 * kp + 1][1], ph[2], pl[2]);
            hilo2(s[2 * kp + 1][2], s[2 * kp + 1][3], ph[3], pl[3]);
            uint32_t kr = (uint32_t)(kp * 16) + a_row;     // kv row within tile
#pragma unroll
            for (int np = 0; np < 4; np++) {
                uint32_t cb = (uint32_t)(np * 32) + a_cb;  // d col bytes
                uint32_t v0, v1, v2, v3, w0, w1, w2, w3;
                ldsm4t(v0, v1, v2, v3, kvb + 2 * FKV_B + fsw(kr, cb));
                ldsm4t(w0, w1, w2, w3, kvb + 3 * FKV_B + fsw(kr, cb));
                uint32_t bh0[2] = {v0, v1}, bh1[2] = {v2, v3};
                uint32_t bl0[2] = {w0, w1}, bl1[2] = {w2, w3};
                mma_bf16(o[np * 2],     ph, bh0);
                mma_bf16(o[np * 2],     ph, bl0);
                mma_bf16(o[np * 2],     pl, bh0);
                mma_bf16(o[np * 2 + 1], ph, bh1);
                mma_bf16(o[np * 2 + 1], ph, bl1);
                mma_bf16(o[np * 2 + 1], pl, bh1);
            }
        }

        __syncthreads();
        if (t + 2 < nt) load_kv(t + 2, t & 1);
        CP_COMMIT();
    }

    // ---- epilogue: O/l -> bf16 hi/lo at [b][s][h*64+d] ----
    const int b = bh >> 4, h = bh & 15;
    const int s0 = q0 + wid * 16 + g;
    const float i0 = 1.f / l0, i1 = 1.f / l1;
#pragma unroll
    for (int dt = 0; dt < 8; dt++) {
        int d = dt * 8 + tig * 2;
        size_t base0 = ((size_t)(b * SEQ) + s0) * HIDDEN + h * HDIM + d;
        size_t base1 = base0 + (size_t)8 * HIDDEN;
        uint32_t hi, lo;
        hilo2(o[dt][0] * i0, o[dt][1] * i0, hi, lo);
        *(uint32_t*)&g_ohi[base0] = hi;  *(uint32_t*)&g_olo[base0] = lo;
        hilo2(o[dt][2] * i1, o[dt][3] * i1, hi, lo);
        *(uint32_t*)&g_ohi[base1] = hi;  *(uint32_t*)&g_olo[base1] = lo;
    }
}

// ---------------------------------------------------------------------------
// Launch
// ---------------------------------------------------------------------------
extern "C" void kernel_launch(void* const* d_in, const int* in_sizes, int n_in,
                              void* d_out, int out_size)
{
    const float* X  = (const float*)d_in[0];
    // d_in[1] = attention_mask (exact causal; applied analytically)
    const float* Wq = (const float*)d_in[2];
    const float* Wk = (const float*)d_in[3];
    const float* Wv = (const float*)d_in[4];
    const float* Wo = (const float*)d_in[5];
    float* out = (float*)d_out;

    cudaFuncSetAttribute(gemm_qkv, cudaFuncAttributeMaxDynamicSharedMemorySize, GSMEM);
    cudaFuncSetAttribute(gemm_out, cudaFuncAttributeMaxDynamicSharedMemorySize, GSMEM);
    cudaFuncSetAttribute(flash_tc, cudaFuncAttributeMaxDynamicSharedMemorySize, FSMEM);

    convert_x<<<NTOK * HIDDEN / 1024, 256>>>(X);
    transpose_w<<<dim3(32, 32, 4), dim3(32, 8)>>>(Wq, Wk, Wv, Wo);

    gemm_qkv<<<dim3(HIDDEN / 128, NTOK / 256, 3), 256, GSMEM>>>();

    flash_tc<<<dim3(SEQ / 128, BATCH * HEADS), 256, FSMEM>>>();

    gemm_out<<<dim3(HIDDEN / 128, NTOK / 256), 256, GSMEM>>>(out);
}

// round 8
// speedup vs baseline: 2.8329x; 1.0725x over previous
#include <cuda_runtime.h>
#include <cuda_bf16.h>
#include <cstdint>

#define BATCH   2
#define SEQ     2048
#define HIDDEN  1024
#define HEADS   16
#define HDIM    64
#define NTOK    (BATCH * SEQ)          // 4096
#define QK_SCALE2 0.18033688f           // 0.125 * log2(e)

typedef __nv_bfloat16 bf16;

// ---------------------------------------------------------------------------
// Device scratch (no cudaMalloc allowed)
// ---------------------------------------------------------------------------
__device__ bf16 s_xhi[NTOK * HIDDEN];               // X split-bf16
__device__ bf16 s_xlo[NTOK * HIDDEN];
__device__ bf16 s_whi[4 * HIDDEN * HIDDEN];         // W^T split-bf16 (q,k,v,o)
__device__ bf16 s_wlo[4 * HIDDEN * HIDDEN];
__device__ bf16 g_qhi[BATCH * HEADS * SEQ * HDIM];  // [B,H,S,D]
__device__ bf16 g_qlo[BATCH * HEADS * SEQ * HDIM];
__device__ bf16 g_khi[BATCH * HEADS * SEQ * HDIM];
__device__ bf16 g_klo[BATCH * HEADS * SEQ * HDIM];
__device__ bf16 g_vhi[BATCH * HEADS * SEQ * HDIM];
__device__ bf16 g_vlo[BATCH * HEADS * SEQ * HDIM];
__device__ bf16 g_ohi[NTOK * HIDDEN];               // attention out [B,S,H*D]
__device__ bf16 g_olo[NTOK * HIDDEN];

// ---------------------------------------------------------------------------
// PTX helpers
// ---------------------------------------------------------------------------
__device__ __forceinline__ uint32_t smem_u32(const void* p) {
    uint32_t a;
    asm("{ .reg .u64 t; cvta.to.shared.u64 t, %1; cvt.u32.u64 %0, t; }" : "=r"(a) : "l"(p));
    return a;
}
__device__ __forceinline__ void cp16(uint32_t s, const void* g) {
    asm volatile("cp.async.cg.shared.global [%0], [%1], 16;" :: "r"(s), "l"(g) : "memory");
}
#define CP_COMMIT() asm volatile("cp.async.commit_group;" ::: "memory")
#define CP_WAIT0()  asm volatile("cp.async.wait_group 0;" ::: "memory")
#define CP_WAIT1()  asm volatile("cp.async.wait_group 1;" ::: "memory")

__device__ __forceinline__ void ldsm4(uint32_t& r0, uint32_t& r1, uint32_t& r2, uint32_t& r3, uint32_t a) {
    asm volatile("ldmatrix.sync.aligned.m8n8.x4.shared.b16 {%0,%1,%2,%3}, [%4];"
                 : "=r"(r0), "=r"(r1), "=r"(r2), "=r"(r3) : "r"(a));
}
__device__ __forceinline__ void ldsm4t(uint32_t& r0, uint32_t& r1, uint32_t& r2, uint32_t& r3, uint32_t a) {
    asm volatile("ldmatrix.sync.aligned.m8n8.x4.trans.shared.b16 {%0,%1,%2,%3}, [%4];"
                 : "=r"(r0), "=r"(r1), "=r"(r2), "=r"(r3) : "r"(a));
}
__device__ __forceinline__ void mma_bf16(float d[4], const uint32_t a[4], const uint32_t b[2]) {
    asm volatile(
        "mma.sync.aligned.m16n8k16.row.col.f32.bf16.bf16.f32 "
        "{%0,%1,%2,%3}, {%4,%5,%6,%7}, {%8,%9}, {%0,%1,%2,%3};"
        : "+f"(d[0]), "+f"(d[1]), "+f"(d[2]), "+f"(d[3])
        : "r"(a[0]), "r"(a[1]), "r"(a[2]), "r"(a[3]), "r"(b[0]), "r"(b[1]));
}
// split x,y into packed bf16 hi pair + lo pair
__device__ __forceinline__ void hilo2(float x, float y, uint32_t& hi, uint32_t& lo) {
    __nv_bfloat16 hx = __float2bfloat16_rn(x), hy = __float2bfloat16_rn(y);
    float rx = x - __bfloat162float(hx), ry = y - __bfloat162float(hy);
    __nv_bfloat16 lx = __float2bfloat16_rn(rx), ly = __float2bfloat16_rn(ry);
    hi = (uint32_t)__bfloat16_as_ushort(hx) | ((uint32_t)__bfloat16_as_ushort(hy) << 16);
    lo = (uint32_t)__bfloat16_as_ushort(lx) | ((uint32_t)__bfloat16_as_ushort(ly) << 16);
}

// ---------------------------------------------------------------------------
// Pre-convert kernels
// ---------------------------------------------------------------------------
__global__ __launch_bounds__(256) void convert_x(const float* __restrict__ X) {
    size_t i4 = ((size_t)blockIdx.x * 256 + threadIdx.x) * 4;
    float4 v = *(const float4*)&X[i4];
    uint32_t h0, l0, h1, l1;
    hilo2(v.x, v.y, h0, l0);
    hilo2(v.z, v.w, h1, l1);
    *(uint32_t*)&s_xhi[i4]     = h0;  *(uint32_t*)&s_xhi[i4 + 2] = h1;
    *(uint32_t*)&s_xlo[i4]     = l0;  *(uint32_t*)&s_xlo[i4 + 2] = l1;
}

// W [k][n] -> Wt [n][k] split-bf16, 32x32 tiles
__global__ __launch_bounds__(256) void transpose_w(
    const float* __restrict__ w0, const float* __restrict__ w1,
    const float* __restrict__ w2, const float* __restrict__ w3)
{
    __shared__ float t[32][33];
    const int z = blockIdx.z;
    const float* W = (z == 0) ? w0 : (z == 1) ? w1 : (z == 2) ? w2 : w3;
    const size_t zoff = (size_t)z * HIDDEN * HIDDEN;
    const int n0 = blockIdx.x * 32, k0 = blockIdx.y * 32;
    const int tx = threadIdx.x, ty = threadIdx.y;   // 32 x 8
#pragma unroll
    for (int i = 0; i < 4; i++)
        t[ty + i * 8][tx] = W[(size_t)(k0 + ty + i * 8) * HIDDEN + n0 + tx];
    __syncthreads();
#pragma unroll
    for (int i = 0; i < 4; i++) {
        int nr = ty + i * 8;
        float v = t[tx][nr];
        bf16 h = __float2bfloat16_rn(v);
        bf16 l = __float2bfloat16_rn(v - __bfloat162float(h));
        s_whi[zoff + (size_t)(n0 + nr) * HIDDEN + k0 + tx] = h;
        s_wlo[zoff + (size_t)(n0 + nr) * HIDDEN + k0 + tx] = l;
    }
}

// ---------------------------------------------------------------------------
// Split-bf16 GEMM: C[4096x1024] = A @ Wt^T ; A,Wt row-major bf16 hi/lo.
// Block 128x128xBK32, 2-stage cp.async, ldmatrix, 8 warps, 2 CTAs/SM.
// ---------------------------------------------------------------------------
#define GBK     32
#define GKITERS (HIDDEN / GBK)          // 32
#define GSTR    80                      // bytes per smem row (40 bf16, pad)
#define GT_B    (128 * GSTR)            // 10240 per matrix tile
#define OA_HI   0
#define OA_LO   GT_B
#define OB_HI   (2 * GT_B)
#define OB_LO   (3 * GT_B)
#define GSTAGE_B (4 * GT_B)             // 40960
#define GSMEM   (2 * GSTAGE_B)          // 81920 (x2 CTAs = 160K)

__device__ __forceinline__ void gemm_load_stage(
    uint32_t sb, const bf16* __restrict__ Ahi, const bf16* __restrict__ Alo,
    const bf16* __restrict__ Bhi, const bf16* __restrict__ Blo,
    int row0, int col0, int kc, int tid)
{
    const int k0 = kc * GBK;
#pragma unroll
    for (int i = 0; i < 2; i++) {
        int idx = tid + i * 256;        // 512 chunks per matrix
        int r = idx >> 2, c = idx & 3;  // r 0..127, c 0..3 (16B chunks)
        uint32_t so = (uint32_t)(r * GSTR + c * 16);
        size_t ga = (size_t)(row0 + r) * HIDDEN + k0 + c * 8;
        size_t gb = (size_t)(col0 + r) * HIDDEN + k0 + c * 8;
        cp16(sb + OA_HI + so, &Ahi[ga]);
        cp16(sb + OA_LO + so, &Alo[ga]);
        cp16(sb + OB_HI + so, &Bhi[gb]);
        cp16(sb + OB_LO + so, &Blo[gb]);
    }
}

__device__ __forceinline__ void gemm_body(
    const bf16* __restrict__ Ahi, const bf16* __restrict__ Alo,
    const bf16* __restrict__ Bhi, const bf16* __restrict__ Blo,
    bf16* __restrict__ OutHi, bf16* __restrict__ OutLo,   // mode qkv (permuted)
    float* __restrict__ OutF)                             // mode fp32 row-major
{
    extern __shared__ __align__(16) char gsm[];
    const uint32_t sb0 = smem_u32(gsm);

    const int tid = threadIdx.x;
    const int lane = tid & 31;
    const int wid = tid >> 5;
    const int g = lane >> 2, tig = lane & 3;
    const int warp_m = wid >> 2;       // 0..1 (64 rows)
    const int warp_n = wid & 3;        // 0..3 (32 cols)
    const int row0 = blockIdx.y * 128;
    const int col0 = blockIdx.x * 128;

    float acc[4][4][4];
#pragma unroll
    for (int mi = 0; mi < 4; mi++)
#pragma unroll
        for (int ni = 0; ni < 4; ni++)
#pragma unroll
            for (int e = 0; e < 4; e++) acc[mi][ni][e] = 0.f;

    gemm_load_stage(sb0, Ahi, Alo, Bhi, Blo, row0, col0, 0, tid);
    CP_COMMIT();

    const uint32_t a_row = (uint32_t)(((lane >> 3) & 1) * 8 + (lane & 7));
    const uint32_t a_cb  = (uint32_t)((lane >> 4) * 16);
    const uint32_t b_row = (uint32_t)((lane >> 4) * 8 + (lane & 7));
    const uint32_t b_cb  = (uint32_t)(((lane >> 3) & 1) * 16);

    for (int kc = 0; kc < GKITERS; kc++) {
        CP_WAIT0();
        __syncthreads();
        if (kc + 1 < GKITERS)
            gemm_load_stage(sb0 + ((kc + 1) & 1) * GSTAGE_B, Ahi, Alo, Bhi, Blo,
                            row0, col0, kc + 1, tid);
        CP_COMMIT();

        const uint32_t sb = sb0 + (kc & 1) * GSTAGE_B;
#pragma unroll
        for (int ks = 0; ks < 2; ks++) {           // two k16 slices
            const uint32_t cbA = (uint32_t)(ks * 32) + a_cb;
            const uint32_t cbB = (uint32_t)(ks * 32) + b_cb;
            uint32_t ah[4][4], al[4][4];
#pragma unroll
            for (int mi = 0; mi < 4; mi++) {
                uint32_t r = (uint32_t)(warp_m * 64 + mi * 16) + a_row;
                uint32_t ad = sb + r * GSTR + cbA;
                ldsm4(ah[mi][0], ah[mi][1], ah[mi][2], ah[mi][3], ad + OA_HI);
                ldsm4(al[mi][0], al[mi][1], al[mi][2], al[mi][3], ad + OA_LO);
            }
#pragma unroll
            for (int np = 0; np < 2; np++) {       // n16 pairs
                uint32_t n = (uint32_t)(warp_n * 32 + np * 16) + b_row;
                uint32_t bd = sb + n * GSTR + cbB;
                uint32_t h0, h1, h2, h3, l0, l1, l2, l3;
                ldsm4(h0, h1, h2, h3, bd + OB_HI);
                ldsm4(l0, l1, l2, l3, bd + OB_LO);
                uint32_t bh0[2] = {h0, h1}, bh1[2] = {h2, h3};
                uint32_t bl0[2] = {l0, l1}, bl1[2] = {l2, l3};
#pragma unroll
                for (int mi = 0; mi < 4; mi++) {
                    mma_bf16(acc[mi][np * 2],     ah[mi], bh0);
                    mma_bf16(acc[mi][np * 2],     ah[mi], bl0);
                    mma_bf16(acc[mi][np * 2],     al[mi], bh0);
                    mma_bf16(acc[mi][np * 2 + 1], ah[mi], bh1);
                    mma_bf16(acc[mi][np * 2 + 1], ah[mi], bl1);
                    mma_bf16(acc[mi][np * 2 + 1], al[mi], bh1);
                }
            }
        }
    }

    // epilogue
#pragma unroll
    for (int mi = 0; mi < 4; mi++) {
        int r = row0 + warp_m * 64 + mi * 16 + g;       // rows r, r+8
#pragma unroll
        for (int ni = 0; ni < 4; ni++) {
            int col = col0 + warp_n * 32 + ni * 8 + tig * 2;
            if (OutF) {
                *(float2*)&OutF[(size_t)r * HIDDEN + col] =
                    make_float2(acc[mi][ni][0], acc[mi][ni][1]);
                *(float2*)&OutF[(size_t)(r + 8) * HIDDEN + col] =
                    make_float2(acc[mi][ni][2], acc[mi][ni][3]);
            } else {
                int h = col >> 6, d = col & 63;
                int b0 = r >> 11, s0 = r & 2047;
                int b1 = (r + 8) >> 11, s1 = (r + 8) & 2047;
                size_t i0 = (((size_t)(b0 * HEADS + h)) * SEQ + s0) * HDIM + d;
                size_t i1 = (((size_t)(b1 * HEADS + h)) * SEQ + s1) * HDIM + d;
                uint32_t hi, lo;
                hilo2(acc[mi][ni][0], acc[mi][ni][1], hi, lo);
                *(uint32_t*)&OutHi[i0] = hi;  *(uint32_t*)&OutLo[i0] = lo;
                hilo2(acc[mi][ni][2], acc[mi][ni][3], hi, lo);
                *(uint32_t*)&OutHi[i1] = hi;  *(uint32_t*)&OutLo[i1] = lo;
            }
        }
    }
}

__global__ __launch_bounds__(256, 2) void gemm_qkv() {
    const int z = blockIdx.z;
    const size_t zoff = (size_t)z * HIDDEN * HIDDEN;
    bf16* oh = (z == 0) ? g_qhi : (z == 1) ? g_khi : g_vhi;
    bf16* ol = (z == 0) ? g_qlo : (z == 1) ? g_klo : g_vlo;
    gemm_body(s_xhi, s_xlo, s_whi + zoff, s_wlo + zoff, oh, ol, nullptr);
}
__global__ __launch_bounds__(256, 2) void gemm_out(float* __restrict__ out) {
    const size_t zoff = (size_t)3 * HIDDEN * HIDDEN;
    gemm_body(g_ohi, g_olo, s_whi + zoff, s_wlo + zoff, nullptr, nullptr, out);
}

// ---------------------------------------------------------------------------
// Flash attention, split-bf16, software-pipelined lookahead:
//   iter t: [issue S(t+1) MMAs] -> softmax(t) overlaps -> PV(t) MMAs
// Br=128, Bc=64, 8 warps, 3 KV smem buffers, 1 CTA/SM.
// ---------------------------------------------------------------------------
#define FQ_B   (128 * 128)              // 16384 bytes per Q matrix
#define FKV_B  (64 * 128)               // 8192 per KV matrix
#define OQH    0
#define OQL    FQ_B
#define OKV    (2 * FQ_B)
#define FSTAGE_B (4 * FKV_B)            // KH,KL,VH,VL = 32768
#define FNBUF  3
#define FSMEM  (2 * FQ_B + FNBUF * FSTAGE_B)   // 131072

// 128B rows, XOR swizzle on the 16B column within the row
__device__ __forceinline__ uint32_t fsw(uint32_t r, uint32_t cb) {
    return r * 128u + ((((cb >> 4) ^ r) & 7u) << 4);
}

__global__ __launch_bounds__(256) void flash_tc()
{
    extern __shared__ __align__(16) char fsm[];
    const uint32_t sb = smem_u32(fsm);

    const int tid = threadIdx.x;
    const int lane = tid & 31;
    const int wid = tid >> 5;
    const int g = lane >> 2, tig = lane & 3;
    const int bh = blockIdx.y;
    const int bx = gridDim.x - 1 - (int)blockIdx.x;   // heavy blocks first
    const int q0 = bx * 128;
    const size_t bho = (size_t)bh * SEQ * HDIM;
    const int nt = 2 * bx + 2;

    // ---- prologue loads ----
    {
        const bf16* qsrc[2] = {g_qhi + bho, g_qlo + bho};
#pragma unroll
        for (int m = 0; m < 2; m++)
#pragma unroll
            for (int i = 0; i < 4; i++) {
                int idx = tid + i * 256;           // 1024 chunks
                int r = idx >> 3, c = idx & 7;
                cp16(sb + (m ? OQL : OQH) + fsw(r, c * 16),
                     qsrc[m] + (size_t)(q0 + r) * HDIM + c * 8);
            }
    }
    auto load_kv = [&](int t, int buf) {
        const int j0 = t * 64;
        const bf16* src[4] = {g_khi + bho, g_klo + bho, g_vhi + bho, g_vlo + bho};
        uint32_t base = sb + OKV + buf * FSTAGE_B;
#pragma unroll
        for (int m = 0; m < 4; m++)
#pragma unroll
            for (int i = 0; i < 2; i++) {
                int idx = tid + i * 256;           // 512 chunks per matrix
                int r = idx >> 3, c = idx & 7;
                cp16(base + m * FKV_B + fsw(r, c * 16),
                     src[m] + (size_t)(j0 + r) * HDIM + c * 8);
            }
    };
    load_kv(0, 0);
    CP_COMMIT();                        // group: Q + KV0
    load_kv(1, 1);
    CP_COMMIT();                        // group: KV1

    const uint32_t a_row = (uint32_t)(((lane >> 3) & 1) * 8 + (lane & 7));
    const uint32_t a_cb  = (uint32_t)((lane >> 4) * 16);
    const uint32_t b_row = (uint32_t)((lane >> 4) * 8 + (lane & 7));
    const uint32_t b_cb  = (uint32_t)(((lane >> 3) & 1) * 16);
    const uint32_t q_row = (uint32_t)(wid * 16) + a_row;

    // issue all 96 S MMAs for a tile from KV buffer `buf` into dst
    auto S_mmas = [&](float (&dst)[8][4], int buf) {
        const uint32_t kvb = sb + OKV + buf * FSTAGE_B;
#pragma unroll
        for (int j = 0; j < 8; j++)
#pragma unroll
            for (int e = 0; e < 4; e++) dst[j][e] = 0.f;
#pragma unroll
        for (int ks = 0; ks < 4; ks++) {
            const uint32_t cbq = (uint32_t)(ks * 32) + a_cb;
            uint32_t qh[4], ql[4];
            ldsm4(qh[0], qh[1], qh[2], qh[3], sb + OQH + fsw(q_row, cbq));
            ldsm4(ql[0], ql[1], ql[2], ql[3], sb + OQL + fsw(q_row, cbq));
            const uint32_t cb = (uint32_t)(ks * 32) + b_cb;
#pragma unroll
            for (int np = 0; np < 4; np++) {
                uint32_t n = (uint32_t)(np * 16) + b_row;
                uint32_t h0, h1, h2, h3, l0r, l1r, l2r, l3r;
                ldsm4(h0, h1, h2, h3, kvb + 0 * FKV_B + fsw(n, cb));
                ldsm4(l0r, l1r, l2r, l3r, kvb + 1 * FKV_B + fsw(n, cb));
                uint32_t bh0[2] = {h0, h1}, bh1[2] = {h2, h3};
                uint32_t bl0[2] = {l0r, l1r}, bl1[2] = {l2r, l3r};
                mma_bf16(dst[np * 2],     qh, bh0);
                mma_bf16(dst[np * 2],     qh, bl0);
                mma_bf16(dst[np * 2],     ql, bh0);
                mma_bf16(dst[np * 2 + 1], qh, bh1);
                mma_bf16(dst[np * 2 + 1], qh, bl1);
                mma_bf16(dst[np * 2 + 1], ql, bh1);
            }
        }
    };

    float m0 = -1e30f, m1 = -1e30f, l0 = 0.f, l1 = 0.f;
    float o[8][4];
#pragma unroll
    for (int dt = 0; dt < 8; dt++)
#pragma unroll
        for (int e = 0; e < 4; e++) o[dt][e] = 0.f;

    float sA[8][4], sB[8][4];

    // wait Q+KV0, compute S(0)
    CP_WAIT1();
    __syncthreads();
    S_mmas(sA, 0);

    // one pipeline iteration: cur = S(t) scores; nxt receives S(t+1)
    auto body = [&](int t, float (&cur)[8][4], float (&nxt)[8][4]) {
        const bool haveNext = (t + 1 < nt);
        // KV(t+1) (issued >=1 iter ago) must be complete + visible
        CP_WAIT0();
        __syncthreads();
        if (t + 2 < nt) load_kv(t + 2, (t + 2) % FNBUF);
        CP_COMMIT();

        // 1) issue next tile's S MMAs (independent of softmax below)
        if (haveNext) S_mmas(nxt, (t + 1) % FNBUF);

        // 2) softmax(t) on cur — runs on MUFU/ALU while S MMAs drain
        const bool masked = (t >= 2 * bx);
        const int j0 = t * 64;
        const int r0 = q0 + wid * 16 + g;
#pragma unroll
        for (int j = 0; j < 8; j++) {
#pragma unroll
            for (int e = 0; e < 4; e++) {
                float v = cur[j][e] * QK_SCALE2;   // scale includes log2(e)
                if (masked) {
                    int col = j0 + j * 8 + tig * 2 + (e & 1);
                    int row = r0 + ((e >> 1) * 8);
                    if (col > row) v = -1e9f;
                }
                cur[j][e] = v;
            }
        }
        float mx0 = -1e30f, mx1 = -1e30f;
#pragma unroll
        for (int j = 0; j < 8; j++) {
            mx0 = fmaxf(mx0, fmaxf(cur[j][0], cur[j][1]));
            mx1 = fmaxf(mx1, fmaxf(cur[j][2], cur[j][3]));
        }
        mx0 = fmaxf(mx0, __shfl_xor_sync(0xffffffffu, mx0, 1));
        mx0 = fmaxf(mx0, __shfl_xor_sync(0xffffffffu, mx0, 2));
        mx1 = fmaxf(mx1, __shfl_xor_sync(0xffffffffu, mx1, 1));
        mx1 = fmaxf(mx1, __shfl_xor_sync(0xffffffffu, mx1, 2));
        float mn0 = fmaxf(m0, mx0), mn1 = fmaxf(m1, mx1);
        float al0 = exp2f(m0 - mn0), al1 = exp2f(m1 - mn1);
        float sum0 = 0.f, sum1 = 0.f;
#pragma unroll
        for (int j = 0; j < 8; j++) {
            cur[j][0] = exp2f(cur[j][0] - mn0); sum0 += cur[j][0];
            cur[j][1] = exp2f(cur[j][1] - mn0); sum0 += cur[j][1];
            cur[j][2] = exp2f(cur[j][2] - mn1); sum1 += cur[j][2];
            cur[j][3] = exp2f(cur[j][3] - mn1); sum1 += cur[j][3];
        }
        sum0 += __shfl_xor_sync(0xffffffffu, sum0, 1);
        sum0 += __shfl_xor_sync(0xffffffffu, sum0, 2);
        sum1 += __shfl_xor_sync(0xffffffffu, sum1, 1);
        sum1 += __shfl_xor_sync(0xffffffffu, sum1, 2);
        l0 = l0 * al0 + sum0;  m0 = mn0;
        l1 = l1 * al1 + sum1;  m1 = mn1;
#pragma unroll
        for (int dt = 0; dt < 8; dt++) {
            o[dt][0] *= al0; o[dt][1] *= al0;
            o[dt][2] *= al1; o[dt][3] *= al1;
        }

        // 3) O += P V from buffer t%3
        const uint32_t kvb = sb + OKV + (t % FNBUF) * FSTAGE_B;
#pragma unroll
        for (int kp = 0; kp < 4; kp++) {
            uint32_t ph[4], pl[4];
            hilo2(cur[2 * kp][0],     cur[2 * kp][1],     ph[0], pl[0]);
            hilo2(cur[2 * kp][2],     cur[2 * kp][3],     ph[1], pl[1]);
            hilo2(cur[2 * kp + 1][0], cur[2 * kp + 1][1], ph[2], pl[2]);
            hilo2(cur[2 * kp + 1][2], cur[2 * kp + 1][3], ph[3], pl[3]);
            uint32_t kr = (uint32_t)(kp * 16) + a_row;     // kv row within tile
#pragma unroll
            for (int np = 0; np < 4; np++) {
                uint32_t cb = (uint32_t)(np * 32) + a_cb;  // d col bytes
                uint32_t v0, v1, v2, v3, w0, w1, w2, w3;
                ldsm4t(v0, v1, v2, v3, kvb + 2 * FKV_B + fsw(kr, cb));
                ldsm4t(w0, w1, w2, w3, kvb + 3 * FKV_B + fsw(kr, cb));
                uint32_t bh0[2] = {v0, v1}, bh1[2] = {v2, v3};
                uint32_t bl0[2] = {w0, w1}, bl1[2] = {w2, w3};
                mma_bf16(o[np * 2],     ph, bh0);
                mma_bf16(o[np * 2],     ph, bl0);
                mma_bf16(o[np * 2],     pl, bh0);
                mma_bf16(o[np * 2 + 1], ph, bh1);
                mma_bf16(o[np * 2 + 1], ph, bl1);
                mma_bf16(o[np * 2 + 1], pl, bh1);
            }
        }
    };

    for (int t = 0; t < nt; t += 2) {
        body(t, sA, sB);
        if (t + 1 < nt) body(t + 1, sB, sA);
    }

    // ---- epilogue: O/l -> bf16 hi/lo at [b][s][h*64+d] ----
    const int b = bh >> 4, h = bh & 15;
    const int s0 = q0 + wid * 16 + g;
    const float i0 = 1.f / l0, i1 = 1.f / l1;
#pragma unroll
    for (int dt = 0; dt < 8; dt++) {
        int d = dt * 8 + tig * 2;
        size_t base0 = ((size_t)(b * SEQ) + s0) * HIDDEN + h * HDIM + d;
        size_t base1 = base0 + (size_t)8 * HIDDEN;
        uint32_t hi, lo;
        hilo2(o[dt][0] * i0, o[dt][1] * i0, hi, lo);
        *(uint32_t*)&g_ohi[base0] = hi;  *(uint32_t*)&g_olo[base0] = lo;
        hilo2(o[dt][2] * i1, o[dt][3] * i1, hi, lo);
        *(uint32_t*)&g_ohi[base1] = hi;  *(uint32_t*)&g_olo[base1] = lo;
    }
}

// ---------------------------------------------------------------------------
// Launch
// ---------------------------------------------------------------------------
extern "C" void kernel_launch(void* const* d_in, const int* in_sizes, int n_in,
                              void* d_out, int out_size)
{
    const float* X  = (const float*)d_in[0];
    // d_in[1] = attention_mask (exact causal; applied analytically)
    const float* Wq = (const float*)d_in[2];
    const float* Wk = (const float*)d_in[3];
    const float* Wv = (const float*)d_in[4];
    const float* Wo = (const float*)d_in[5];
    float* out = (float*)d_out;

    cudaFuncSetAttribute(gemm_qkv, cudaFuncAttributeMaxDynamicSharedMemorySize, GSMEM);
    cudaFuncSetAttribute(gemm_out, cudaFuncAttributeMaxDynamicSharedMemorySize, GSMEM);
    cudaFuncSetAttribute(flash_tc, cudaFuncAttributeMaxDynamicSharedMemorySize, FSMEM);

    convert_x<<<NTOK * HIDDEN / 1024, 256>>>(X);
    transpose_w<<<dim3(32, 32, 4), dim3(32, 8)>>>(Wq, Wk, Wv, Wo);

    gemm_qkv<<<dim3(HIDDEN / 128, NTOK / 128, 3), 256, GSMEM>>>();

    flash_tc<<<dim3(SEQ / 128, BATCH * HEADS), 256, FSMEM>>>();

    gemm_out<<<dim3(HIDDEN / 128, NTOK / 128), 256, GSMEM>>>(out);
}

// round 9
// speedup vs baseline: 2.9873x; 1.0545x over previous
#include <cuda_runtime.h>
#include <cuda_bf16.h>
#include <cstdint>

#define BATCH   2
#define SEQ     2048
#define HIDDEN  1024
#define HEADS   16
#define HDIM    64
#define NTOK    (BATCH * SEQ)          // 4096
#define QK_SCALE2 0.18033688f           // 0.125 * log2(e)

typedef __nv_bfloat16 bf16;

// ---------------------------------------------------------------------------
// Device scratch (no cudaMalloc allowed)
// ---------------------------------------------------------------------------
__device__ bf16 s_xhi[NTOK * HIDDEN];               // X split-bf16
__device__ bf16 s_xlo[NTOK * HIDDEN];
__device__ bf16 s_whi[4 * HIDDEN * HIDDEN];         // W^T split-bf16 (q,k,v,o)
__device__ bf16 s_wlo[4 * HIDDEN * HIDDEN];
__device__ bf16 g_qhi[BATCH * HEADS * SEQ * HDIM];  // [B,H,S,D] (Q pre-scaled)
__device__ bf16 g_qlo[BATCH * HEADS * SEQ * HDIM];
__device__ bf16 g_khi[BATCH * HEADS * SEQ * HDIM];
__device__ bf16 g_klo[BATCH * HEADS * SEQ * HDIM];
__device__ bf16 g_vhi[BATCH * HEADS * SEQ * HDIM];
__device__ bf16 g_vlo[BATCH * HEADS * SEQ * HDIM];
__device__ bf16 g_ohi[NTOK * HIDDEN];               // attention out [B,S,H*D]
__device__ bf16 g_olo[NTOK * HIDDEN];

// ---------------------------------------------------------------------------
// PTX helpers
// ---------------------------------------------------------------------------
__device__ __forceinline__ uint32_t smem_u32(const void* p) {
    uint32_t a;
    asm("{ .reg .u64 t; cvta.to.shared.u64 t, %1; cvt.u32.u64 %0, t; }" : "=r"(a) : "l"(p));
    return a;
}
__device__ __forceinline__ void cp16(uint32_t s, const void* g) {
    asm volatile("cp.async.cg.shared.global [%0], [%1], 16;" :: "r"(s), "l"(g) : "memory");
}
#define CP_COMMIT() asm volatile("cp.async.commit_group;" ::: "memory")
#define CP_WAIT0()  asm volatile("cp.async.wait_group 0;" ::: "memory")
#define CP_WAIT1()  asm volatile("cp.async.wait_group 1;" ::: "memory")

__device__ __forceinline__ void ldsm4(uint32_t& r0, uint32_t& r1, uint32_t& r2, uint32_t& r3, uint32_t a) {
    asm volatile("ldmatrix.sync.aligned.m8n8.x4.shared.b16 {%0,%1,%2,%3}, [%4];"
                 : "=r"(r0), "=r"(r1), "=r"(r2), "=r"(r3) : "r"(a));
}
__device__ __forceinline__ void ldsm4t(uint32_t& r0, uint32_t& r1, uint32_t& r2, uint32_t& r3, uint32_t a) {
    asm volatile("ldmatrix.sync.aligned.m8n8.x4.trans.shared.b16 {%0,%1,%2,%3}, [%4];"
                 : "=r"(r0), "=r"(r1), "=r"(r2), "=r"(r3) : "r"(a));
}
__device__ __forceinline__ void mma_bf16(float d[4], const uint32_t a[4], const uint32_t b[2]) {
    asm volatile(
        "mma.sync.aligned.m16n8k16.row.col.f32.bf16.bf16.f32 "
        "{%0,%1,%2,%3}, {%4,%5,%6,%7}, {%8,%9}, {%0,%1,%2,%3};"
        : "+f"(d[0]), "+f"(d[1]), "+f"(d[2]), "+f"(d[3])
        : "r"(a[0]), "r"(a[1]), "r"(a[2]), "r"(a[3]), "r"(b[0]), "r"(b[1]));
}
// split x,y into packed bf16 hi pair + lo pair (packed cvt: ~6 instrs)
__device__ __forceinline__ void hilo2(float x, float y, uint32_t& hi, uint32_t& lo) {
    __nv_bfloat162 h2 = __floats2bfloat162_rn(x, y);   // x->low, y->high
    float rx = x - __bfloat162float(h2.x);
    float ry = y - __bfloat162float(h2.y);
    __nv_bfloat162 l2 = __floats2bfloat162_rn(rx, ry);
    hi = *reinterpret_cast<uint32_t*>(&h2);
    lo = *reinterpret_cast<uint32_t*>(&l2);
}

// ---------------------------------------------------------------------------
// Pre-convert kernels
// ---------------------------------------------------------------------------
__global__ __launch_bounds__(256) void convert_x(const float* __restrict__ X) {
    size_t i4 = ((size_t)blockIdx.x * 256 + threadIdx.x) * 4;
    float4 v = *(const float4*)&X[i4];
    uint32_t h0, l0, h1, l1;
    hilo2(v.x, v.y, h0, l0);
    hilo2(v.z, v.w, h1, l1);
    *(uint32_t*)&s_xhi[i4]     = h0;  *(uint32_t*)&s_xhi[i4 + 2] = h1;
    *(uint32_t*)&s_xlo[i4]     = l0;  *(uint32_t*)&s_xlo[i4 + 2] = l1;
}

// W [k][n] -> Wt [n][k] split-bf16, 32x32 tiles
__global__ __launch_bounds__(256) void transpose_w(
    const float* __restrict__ w0, const float* __restrict__ w1,
    const float* __restrict__ w2, const float* __restrict__ w3)
{
    __shared__ float t[32][33];
    const int z = blockIdx.z;
    const float* W = (z == 0) ? w0 : (z == 1) ? w1 : (z == 2) ? w2 : w3;
    const size_t zoff = (size_t)z * HIDDEN * HIDDEN;
    const int n0 = blockIdx.x * 32, k0 = blockIdx.y * 32;
    const int tx = threadIdx.x, ty = threadIdx.y;   // 32 x 8
#pragma unroll
    for (int i = 0; i < 4; i++)
        t[ty + i * 8][tx] = W[(size_t)(k0 + ty + i * 8) * HIDDEN + n0 + tx];
    __syncthreads();
#pragma unroll
    for (int i = 0; i < 4; i++) {
        int nr = ty + i * 8;
        float v = t[tx][nr];
        bf16 h = __float2bfloat16_rn(v);
        bf16 l = __float2bfloat16_rn(v - __bfloat162float(h));
        s_whi[zoff + (size_t)(n0 + nr) * HIDDEN + k0 + tx] = h;
        s_wlo[zoff + (size_t)(n0 + nr) * HIDDEN + k0 + tx] = l;
    }
}

// ---------------------------------------------------------------------------
// Split-bf16 GEMM: C[4096x1024] = A @ Wt^T ; A,Wt row-major bf16 hi/lo.
// Block 128x128xBK32, 2-stage cp.async, 4 warps (warp tile 64x64), 2 CTAs/SM.
// ---------------------------------------------------------------------------
#define GBK     32
#define GKITERS (HIDDEN / GBK)          // 32
#define GSTR    80                      // bytes per smem row (40 bf16, pad)
#define GT_B    (128 * GSTR)            // 10240 per matrix tile
#define OA_HI   0
#define OA_LO   GT_B
#define OB_HI   (2 * GT_B)
#define OB_LO   (3 * GT_B)
#define GSTAGE_B (4 * GT_B)             // 40960
#define GSMEM   (2 * GSTAGE_B)          // 81920 (x2 CTAs = 160K)

__device__ __forceinline__ void gemm_load_stage(
    uint32_t sb, const bf16* __restrict__ Ahi, const bf16* __restrict__ Alo,
    const bf16* __restrict__ Bhi, const bf16* __restrict__ Blo,
    int row0, int col0, int kc, int tid)
{
    const int k0 = kc * GBK;
#pragma unroll
    for (int i = 0; i < 4; i++) {
        int idx = tid + i * 128;        // 512 chunks per matrix
        int r = idx >> 2, c = idx & 3;  // r 0..127, c 0..3 (16B chunks)
        uint32_t so = (uint32_t)(r * GSTR + c * 16);
        size_t ga = (size_t)(row0 + r) * HIDDEN + k0 + c * 8;
        size_t gb = (size_t)(col0 + r) * HIDDEN + k0 + c * 8;
        cp16(sb + OA_HI + so, &Ahi[ga]);
        cp16(sb + OA_LO + so, &Alo[ga]);
        cp16(sb + OB_HI + so, &Bhi[gb]);
        cp16(sb + OB_LO + so, &Blo[gb]);
    }
}

__device__ __forceinline__ void gemm_body(
    const bf16* __restrict__ Ahi, const bf16* __restrict__ Alo,
    const bf16* __restrict__ Bhi, const bf16* __restrict__ Blo,
    bf16* __restrict__ OutHi, bf16* __restrict__ OutLo,   // mode qkv (permuted)
    float* __restrict__ OutF,                             // mode fp32 row-major
    float oscale)
{
    extern __shared__ __align__(16) char gsm[];
    const uint32_t sb0 = smem_u32(gsm);

    const int tid = threadIdx.x;        // 128 threads
    const int lane = tid & 31;
    const int wid = tid >> 5;           // 0..3
    const int g = lane >> 2, tig = lane & 3;
    const int warp_m = wid >> 1;        // 0..1 (64 rows)
    const int warp_n = wid & 1;         // 0..1 (64 cols)
    const int row0 = blockIdx.y * 128;
    const int col0 = blockIdx.x * 128;

    float acc[4][8][4];
#pragma unroll
    for (int mi = 0; mi < 4; mi++)
#pragma unroll
        for (int nj = 0; nj < 8; nj++)
#pragma unroll
            for (int e = 0; e < 4; e++) acc[mi][nj][e] = 0.f;

    gemm_load_stage(sb0, Ahi, Alo, Bhi, Blo, row0, col0, 0, tid);
    CP_COMMIT();

    const uint32_t a_row = (uint32_t)(((lane >> 3) & 1) * 8 + (lane & 7));
    const uint32_t a_cb  = (uint32_t)((lane >> 4) * 16);
    const uint32_t b_row = (uint32_t)((lane >> 4) * 8 + (lane & 7));
    const uint32_t b_cb  = (uint32_t)(((lane >> 3) & 1) * 16);

    for (int kc = 0; kc < GKITERS; kc++) {
        CP_WAIT0();
        __syncthreads();
        if (kc + 1 < GKITERS)
            gemm_load_stage(sb0 + ((kc + 1) & 1) * GSTAGE_B, Ahi, Alo, Bhi, Blo,
                            row0, col0, kc + 1, tid);
        CP_COMMIT();

        const uint32_t sb = sb0 + (kc & 1) * GSTAGE_B;
#pragma unroll
        for (int ks = 0; ks < 2; ks++) {           // two k16 slices
            const uint32_t cbA = (uint32_t)(ks * 32) + a_cb;
            const uint32_t cbB = (uint32_t)(ks * 32) + b_cb;
            uint32_t ah[4][4], al[4][4];
#pragma unroll
            for (int mi = 0; mi < 4; mi++) {
                uint32_t r = (uint32_t)(warp_m * 64 + mi * 16) + a_row;
                uint32_t ad = sb + r * GSTR + cbA;
                ldsm4(ah[mi][0], ah[mi][1], ah[mi][2], ah[mi][3], ad + OA_HI);
                ldsm4(al[mi][0], al[mi][1], al[mi][2], al[mi][3], ad + OA_LO);
            }
#pragma unroll
            for (int np = 0; np < 4; np++) {       // four n16 groups (64 cols)
                uint32_t n = (uint32_t)(warp_n * 64 + np * 16) + b_row;
                uint32_t bd = sb + n * GSTR + cbB;
                uint32_t h0, h1, h2, h3, l0, l1, l2, l3;
                ldsm4(h0, h1, h2, h3, bd + OB_HI);
                ldsm4(l0, l1, l2, l3, bd + OB_LO);
                uint32_t bh0[2] = {h0, h1}, bh1[2] = {h2, h3};
                uint32_t bl0[2] = {l0, l1}, bl1[2] = {l2, l3};
#pragma unroll
                for (int mi = 0; mi < 4; mi++) {
                    mma_bf16(acc[mi][np * 2],     ah[mi], bh0);
                    mma_bf16(acc[mi][np * 2],     ah[mi], bl0);
                    mma_bf16(acc[mi][np * 2],     al[mi], bh0);
                    mma_bf16(acc[mi][np * 2 + 1], ah[mi], bh1);
                    mma_bf16(acc[mi][np * 2 + 1], ah[mi], bl1);
                    mma_bf16(acc[mi][np * 2 + 1], al[mi], bh1);
                }
            }
        }
    }

    // epilogue
#pragma unroll
    for (int mi = 0; mi < 4; mi++) {
        int r = row0 + warp_m * 64 + mi * 16 + g;       // rows r, r+8
#pragma unroll
        for (int nj = 0; nj < 8; nj++) {
            int col = col0 + warp_n * 64 + nj * 8 + tig * 2;
            if (OutF) {
                *(float2*)&OutF[(size_t)r * HIDDEN + col] =
                    make_float2(acc[mi][nj][0], acc[mi][nj][1]);
                *(float2*)&OutF[(size_t)(r + 8) * HIDDEN + col] =
                    make_float2(acc[mi][nj][2], acc[mi][nj][3]);
            } else {
                int h = col >> 6, d = col & 63;
                int b0 = r >> 11, s0 = r & 2047;
                int b1 = (r + 8) >> 11, s1 = (r + 8) & 2047;
                size_t i0 = (((size_t)(b0 * HEADS + h)) * SEQ + s0) * HDIM + d;
                size_t i1 = (((size_t)(b1 * HEADS + h)) * SEQ + s1) * HDIM + d;
                uint32_t hi, lo;
                hilo2(acc[mi][nj][0] * oscale, acc[mi][nj][1] * oscale, hi, lo);
                *(uint32_t*)&OutHi[i0] = hi;  *(uint32_t*)&OutLo[i0] = lo;
                hilo2(acc[mi][nj][2] * oscale, acc[mi][nj][3] * oscale, hi, lo);
                *(uint32_t*)&OutHi[i1] = hi;  *(uint32_t*)&OutLo[i1] = lo;
            }
        }
    }
}

__global__ __launch_bounds__(128) void gemm_qkv() {
    const int z = blockIdx.z;
    const size_t zoff = (size_t)z * HIDDEN * HIDDEN;
    bf16* oh = (z == 0) ? g_qhi : (z == 1) ? g_khi : g_vhi;
    bf16* ol = (z == 0) ? g_qlo : (z == 1) ? g_klo : g_vlo;
    float sc = (z == 0) ? QK_SCALE2 : 1.0f;   // fold softmax scale into Q
    gemm_body(s_xhi, s_xlo, s_whi + zoff, s_wlo + zoff, oh, ol, nullptr, sc);
}
__global__ __launch_bounds__(128) void gemm_out(float* __restrict__ out) {
    const size_t zoff = (size_t)3 * HIDDEN * HIDDEN;
    gemm_body(g_ohi, g_olo, s_whi + zoff, s_wlo + zoff, nullptr, nullptr, out, 1.0f);
}

// ---------------------------------------------------------------------------
// Flash attention, split-bf16, Br=128, Bc=128, 8 warps, 2 KV buffers.
// Q pre-scaled by 0.125*log2(e); softmax in exp2 domain.
// ---------------------------------------------------------------------------
#define FQ_B   (128 * 128)              // 16384 bytes per Q matrix
#define FKV_B  (128 * 128)              // 16384 per KV matrix (128 rows x 128B)
#define OQH    0
#define OQL    FQ_B
#define OKV    (2 * FQ_B)
#define FSTAGE_B (4 * FKV_B)            // KH,KL,VH,VL = 65536
#define FSMEM  (2 * FQ_B + 2 * FSTAGE_B)   // 163840

// 128B rows, XOR swizzle on the 16B column within the row
__device__ __forceinline__ uint32_t fsw(uint32_t r, uint32_t cb) {
    return r * 128u + ((((cb >> 4) ^ r) & 7u) << 4);
}

__global__ __launch_bounds__(256) void flash_tc()
{
    extern __shared__ __align__(16) char fsm[];
    const uint32_t sb = smem_u32(fsm);

    const int tid = threadIdx.x;
    const int lane = tid & 31;
    const int wid = tid >> 5;
    const int g = lane >> 2, tig = lane & 3;
    const int bh = blockIdx.y;
    const int bx = gridDim.x - 1 - (int)blockIdx.x;   // heavy blocks first
    const int q0 = bx * 128;
    const size_t bho = (size_t)bh * SEQ * HDIM;
    const int nt = bx + 1;

    // ---- prologue loads ----
    {
        const bf16* qsrc[2] = {g_qhi + bho, g_qlo + bho};
#pragma unroll
        for (int m = 0; m < 2; m++)
#pragma unroll
            for (int i = 0; i < 4; i++) {
                int idx = tid + i * 256;           // 1024 chunks
                int r = idx >> 3, c = idx & 7;
                cp16(sb + (m ? OQL : OQH) + fsw(r, c * 16),
                     qsrc[m] + (size_t)(q0 + r) * HDIM + c * 8);
            }
    }
    auto load_kv = [&](int t, int buf) {
        const int j0 = t * 128;
        const bf16* src[4] = {g_khi + bho, g_klo + bho, g_vhi + bho, g_vlo + bho};
        uint32_t base = sb + OKV + buf * FSTAGE_B;
#pragma unroll
        for (int m = 0; m < 4; m++)
#pragma unroll
            for (int i = 0; i < 4; i++) {
                int idx = tid + i * 256;           // 1024 chunks per matrix
                int r = idx >> 3, c = idx & 7;
                cp16(base + m * FKV_B + fsw(r, c * 16),
                     src[m] + (size_t)(j0 + r) * HDIM + c * 8);
            }
    };
    load_kv(0, 0);
    CP_COMMIT();                        // group: Q + KV0
    if (nt > 1) load_kv(1, 1);
    CP_COMMIT();                        // group: KV1 (possibly empty)

    const uint32_t a_row = (uint32_t)(((lane >> 3) & 1) * 8 + (lane & 7));
    const uint32_t a_cb  = (uint32_t)((lane >> 4) * 16);
    const uint32_t b_row = (uint32_t)((lane >> 4) * 8 + (lane & 7));
    const uint32_t b_cb  = (uint32_t)(((lane >> 3) & 1) * 16);
    const uint32_t q_row = (uint32_t)(wid * 16) + a_row;

    float m0 = -1e30f, m1 = -1e30f, l0 = 0.f, l1 = 0.f;
    float o[8][4];
#pragma unroll
    for (int dt = 0; dt < 8; dt++)
#pragma unroll
        for (int e = 0; e < 4; e++) o[dt][e] = 0.f;

    for (int t = 0; t < nt; t++) {
        CP_WAIT1();
        __syncthreads();
        const uint32_t kvb = sb + OKV + (t & 1) * FSTAGE_B;

        // ---- S = Q K^T (scores already in log2 domain via pre-scaled Q) ----
        float s[16][4];
#pragma unroll
        for (int j = 0; j < 16; j++)
#pragma unroll
            for (int e = 0; e < 4; e++) s[j][e] = 0.f;
#pragma unroll
        for (int ks = 0; ks < 4; ks++) {
            const uint32_t cbq = (uint32_t)(ks * 32) + a_cb;
            uint32_t qh[4], ql[4];
            ldsm4(qh[0], qh[1], qh[2], qh[3], sb + OQH + fsw(q_row, cbq));
            ldsm4(ql[0], ql[1], ql[2], ql[3], sb + OQL + fsw(q_row, cbq));
            const uint32_t cb = (uint32_t)(ks * 32) + b_cb;
#pragma unroll
            for (int np = 0; np < 8; np++) {
                uint32_t n = (uint32_t)(np * 16) + b_row;
                uint32_t h0, h1, h2, h3, l0r, l1r, l2r, l3r;
                ldsm4(h0, h1, h2, h3, kvb + 0 * FKV_B + fsw(n, cb));
                ldsm4(l0r, l1r, l2r, l3r, kvb + 1 * FKV_B + fsw(n, cb));
                uint32_t bh0[2] = {h0, h1}, bh1[2] = {h2, h3};
                uint32_t bl0[2] = {l0r, l1r}, bl1[2] = {l2r, l3r};
                mma_bf16(s[np * 2],     qh, bh0);
                mma_bf16(s[np * 2],     qh, bl0);
                mma_bf16(s[np * 2],     ql, bh0);
                mma_bf16(s[np * 2 + 1], qh, bh1);
                mma_bf16(s[np * 2 + 1], qh, bl1);
                mma_bf16(s[np * 2 + 1], ql, bh1);
            }
        }

        // ---- causal mask (diagonal tile only; uniform branch) ----
        if (t == bx) {
            const int j0 = t * 128;
            const int r0 = q0 + wid * 16 + g;
#pragma unroll
            for (int j = 0; j < 16; j++) {
#pragma unroll
                for (int e = 0; e < 4; e++) {
                    int col = j0 + j * 8 + tig * 2 + (e & 1);
                    int row = r0 + ((e >> 1) * 8);
                    if (col > row) s[j][e] = -1e9f;
                }
            }
        }

        // ---- online softmax (rows g and g+8), exp2 domain ----
        float mx0 = -1e30f, mx1 = -1e30f;
#pragma unroll
        for (int j = 0; j < 16; j++) {
            mx0 = fmaxf(mx0, fmaxf(s[j][0], s[j][1]));
            mx1 = fmaxf(mx1, fmaxf(s[j][2], s[j][3]));
        }
        mx0 = fmaxf(mx0, __shfl_xor_sync(0xffffffffu, mx0, 1));
        mx0 = fmaxf(mx0, __shfl_xor_sync(0xffffffffu, mx0, 2));
        mx1 = fmaxf(mx1, __shfl_xor_sync(0xffffffffu, mx1, 1));
        mx1 = fmaxf(mx1, __shfl_xor_sync(0xffffffffu, mx1, 2));
        float mn0 = fmaxf(m0, mx0), mn1 = fmaxf(m1, mx1);
        float al0 = exp2f(m0 - mn0), al1 = exp2f(m1 - mn1);
        float sum0 = 0.f, sum1 = 0.f;
#pragma unroll
        for (int j = 0; j < 16; j++) {
            s[j][0] = exp2f(s[j][0] - mn0); sum0 += s[j][0];
            s[j][1] = exp2f(s[j][1] - mn0); sum0 += s[j][1];
            s[j][2] = exp2f(s[j][2] - mn1); sum1 += s[j][2];
            s[j][3] = exp2f(s[j][3] - mn1); sum1 += s[j][3];
        }
        sum0 += __shfl_xor_sync(0xffffffffu, sum0, 1);
        sum0 += __shfl_xor_sync(0xffffffffu, sum0, 2);
        sum1 += __shfl_xor_sync(0xffffffffu, sum1, 1);
        sum1 += __shfl_xor_sync(0xffffffffu, sum1, 2);
        l0 = l0 * al0 + sum0;  m0 = mn0;
        l1 = l1 * al1 + sum1;  m1 = mn1;
#pragma unroll
        for (int dt = 0; dt < 8; dt++) {
            o[dt][0] *= al0; o[dt][1] *= al0;
            o[dt][2] *= al1; o[dt][3] *= al1;
        }

        // ---- O += P V ----
#pragma unroll
        for (int kp = 0; kp < 8; kp++) {
            uint32_t ph[4], pl[4];
            hilo2(s[2 * kp][0],     s[2 * kp][1],     ph[0], pl[0]);
            hilo2(s[2 * kp][2],     s[2 * kp][3],     ph[1], pl[1]);
            hilo2(s[2 * kp + 1][0], s[2 * kp + 1][1], ph[2], pl[2]);
            hilo2(s[2 * kp + 1][2], s[2 * kp + 1][3], ph[3], pl[3]);
            uint32_t kr = (uint32_t)(kp * 16) + a_row;     // kv row within tile
#pragma unroll
            for (int np = 0; np < 4; np++) {
                uint32_t cb = (uint32_t)(np * 32) + a_cb;  // d col bytes
                uint32_t v0, v1, v2, v3, w0, w1, w2, w3;
                ldsm4t(v0, v1, v2, v3, kvb + 2 * FKV_B + fsw(kr, cb));
                ldsm4t(w0, w1, w2, w3, kvb + 3 * FKV_B + fsw(kr, cb));
                uint32_t bh0[2] = {v0, v1}, bh1[2] = {v2, v3};
                uint32_t bl0[2] = {w0, w1}, bl1[2] = {w2, w3};
                mma_bf16(o[np * 2],     ph, bh0);
                mma_bf16(o[np * 2],     ph, bl0);
                mma_bf16(o[np * 2],     pl, bh0);
                mma_bf16(o[np * 2 + 1], ph, bh1);
                mma_bf16(o[np * 2 + 1], ph, bl1);
                mma_bf16(o[np * 2 + 1], pl, bh1);
            }
        }

        __syncthreads();
        if (t + 2 < nt) load_kv(t + 2, t & 1);
        CP_COMMIT();
    }

    // ---- epilogue: O/l -> bf16 hi/lo at [b][s][h*64+d] ----
    const int b = bh >> 4, h = bh & 15;
    const int s0 = q0 + wid * 16 + g;
    const float i0 = 1.f / l0, i1 = 1.f / l1;
#pragma unroll
    for (int dt = 0; dt < 8; dt++) {
        int d = dt * 8 + tig * 2;
        size_t base0 = ((size_t)(b * SEQ) + s0) * HIDDEN + h * HDIM + d;
        size_t base1 = base0 + (size_t)8 * HIDDEN;
        uint32_t hi, lo;
        hilo2(o[dt][0] * i0, o[dt][1] * i0, hi, lo);
        *(uint32_t*)&g_ohi[base0] = hi;  *(uint32_t*)&g_olo[base0] = lo;
        hilo2(o[dt][2] * i1, o[dt][3] * i1, hi, lo);
        *(uint32_t*)&g_ohi[base1] = hi;  *(uint32_t*)&g_olo[base1] = lo;
    }
}

// ---------------------------------------------------------------------------
// Launch
// ---------------------------------------------------------------------------
extern "C" void kernel_launch(void* const* d_in, const int* in_sizes, int n_in,
                              void* d_out, int out_size)
{
    const float* X  = (const float*)d_in[0];
    // d_in[1] = attention_mask (exact causal; applied analytically)
    const float* Wq = (const float*)d_in[2];
    const float* Wk = (const float*)d_in[3];
    const float* Wv = (const float*)d_in[4];
    const float* Wo = (const float*)d_in[5];
    float* out = (float*)d_out;

    cudaFuncSetAttribute(gemm_qkv, cudaFuncAttributeMaxDynamicSharedMemorySize, GSMEM);
    cudaFuncSetAttribute(gemm_out, cudaFuncAttributeMaxDynamicSharedMemorySize, GSMEM);
    cudaFuncSetAttribute(flash_tc, cudaFuncAttributeMaxDynamicSharedMemorySize, FSMEM);

    convert_x<<<NTOK * HIDDEN / 1024, 256>>>(X);
    transpose_w<<<dim3(32, 32, 4), dim3(32, 8)>>>(Wq, Wk, Wv, Wo);

    gemm_qkv<<<dim3(HIDDEN / 128, NTOK / 128, 3), 128, GSMEM>>>();

    flash_tc<<<dim3(SEQ / 128, BATCH * HEADS), 256, FSMEM>>>();

    gemm_out<<<dim3(HIDDEN / 128, NTOK / 128), 128, GSMEM>>>(out);
}

// round 10
// speedup vs baseline: 3.2471x; 1.0870x over previous
#include <cuda_runtime.h>
#include <cuda_bf16.h>
#include <cstdint>

#define BATCH   2
#define SEQ     2048
#define HIDDEN  1024
#define HEADS   16
#define HDIM    64
#define NTOK    (BATCH * SEQ)          // 4096
#define QK_SCALE2 0.18033688f           // 0.125 * log2(e)

typedef __nv_bfloat16 bf16;

// ---------------------------------------------------------------------------
// Device scratch (no cudaMalloc allowed)
// ---------------------------------------------------------------------------
__device__ bf16 s_xhi[NTOK * HIDDEN];               // X split-bf16
__device__ bf16 s_xlo[NTOK * HIDDEN];
__device__ bf16 s_whi[4 * HIDDEN * HIDDEN];         // W^T split-bf16 (q,k,v,o)
__device__ bf16 s_wlo[4 * HIDDEN * HIDDEN];
__device__ bf16 g_qhi[BATCH * HEADS * SEQ * HDIM];  // [B,H,S,D] (Q pre-scaled)
__device__ bf16 g_qlo[BATCH * HEADS * SEQ * HDIM];
__device__ bf16 g_khi[BATCH * HEADS * SEQ * HDIM];
__device__ bf16 g_klo[BATCH * HEADS * SEQ * HDIM];
__device__ bf16 g_vhi[BATCH * HEADS * SEQ * HDIM];
__device__ bf16 g_vlo[BATCH * HEADS * SEQ * HDIM];
__device__ bf16 g_ohi[NTOK * HIDDEN];               // attention out [B,S,H*D]
__device__ bf16 g_olo[NTOK * HIDDEN];

// ---------------------------------------------------------------------------
// PTX helpers
// ---------------------------------------------------------------------------
__device__ __forceinline__ uint32_t smem_u32(const void* p) {
    uint32_t a;
    asm("{ .reg .u64 t; cvta.to.shared.u64 t, %1; cvt.u32.u64 %0, t; }" : "=r"(a) : "l"(p));
    return a;
}
__device__ __forceinline__ void cp16(uint32_t s, const void* g) {
    asm volatile("cp.async.cg.shared.global [%0], [%1], 16;" :: "r"(s), "l"(g) : "memory");
}
#define CP_COMMIT() asm volatile("cp.async.commit_group;" ::: "memory")
#define CP_WAIT0()  asm volatile("cp.async.wait_group 0;" ::: "memory")
#define CP_WAIT1()  asm volatile("cp.async.wait_group 1;" ::: "memory")

__device__ __forceinline__ void ldsm4(uint32_t& r0, uint32_t& r1, uint32_t& r2, uint32_t& r3, uint32_t a) {
    asm volatile("ldmatrix.sync.aligned.m8n8.x4.shared.b16 {%0,%1,%2,%3}, [%4];"
                 : "=r"(r0), "=r"(r1), "=r"(r2), "=r"(r3) : "r"(a));
}
__device__ __forceinline__ void ldsm4t(uint32_t& r0, uint32_t& r1, uint32_t& r2, uint32_t& r3, uint32_t a) {
    asm volatile("ldmatrix.sync.aligned.m8n8.x4.trans.shared.b16 {%0,%1,%2,%3}, [%4];"
                 : "=r"(r0), "=r"(r1), "=r"(r2), "=r"(r3) : "r"(a));
}
__device__ __forceinline__ void mma_bf16(float d[4], const uint32_t a[4], const uint32_t b[2]) {
    asm volatile(
        "mma.sync.aligned.m16n8k16.row.col.f32.bf16.bf16.f32 "
        "{%0,%1,%2,%3}, {%4,%5,%6,%7}, {%8,%9}, {%0,%1,%2,%3};"
        : "+f"(d[0]), "+f"(d[1]), "+f"(d[2]), "+f"(d[3])
        : "r"(a[0]), "r"(a[1]), "r"(a[2]), "r"(a[3]), "r"(b[0]), "r"(b[1]));
}
// split x,y into packed bf16 hi pair + lo pair (packed cvt)
__device__ __forceinline__ void hilo2(float x, float y, uint32_t& hi, uint32_t& lo) {
    __nv_bfloat162 h2 = __floats2bfloat162_rn(x, y);   // x->low, y->high
    float rx = x - __bfloat162float(h2.x);
    float ry = y - __bfloat162float(h2.y);
    __nv_bfloat162 l2 = __floats2bfloat162_rn(rx, ry);
    hi = *reinterpret_cast<uint32_t*>(&h2);
    lo = *reinterpret_cast<uint32_t*>(&l2);
}

// ---------------------------------------------------------------------------
// Pre-convert kernels
// ---------------------------------------------------------------------------
__global__ __launch_bounds__(256) void convert_x(const float* __restrict__ X) {
    size_t i4 = ((size_t)blockIdx.x * 256 + threadIdx.x) * 4;
    float4 v = *(const float4*)&X[i4];
    uint32_t h0, l0, h1, l1;
    hilo2(v.x, v.y, h0, l0);
    hilo2(v.z, v.w, h1, l1);
    *(uint32_t*)&s_xhi[i4]     = h0;  *(uint32_t*)&s_xhi[i4 + 2] = h1;
    *(uint32_t*)&s_xlo[i4]     = l0;  *(uint32_t*)&s_xlo[i4 + 2] = l1;
}

// W [k][n] -> Wt [n][k] split-bf16, 32x32 tiles
__global__ __launch_bounds__(256) void transpose_w(
    const float* __restrict__ w0, const float* __restrict__ w1,
    const float* __restrict__ w2, const float* __restrict__ w3)
{
    __shared__ float t[32][33];
    const int z = blockIdx.z;
    const float* W = (z == 0) ? w0 : (z == 1) ? w1 : (z == 2) ? w2 : w3;
    const size_t zoff = (size_t)z * HIDDEN * HIDDEN;
    const int n0 = blockIdx.x * 32, k0 = blockIdx.y * 32;
    const int tx = threadIdx.x, ty = threadIdx.y;   // 32 x 8
#pragma unroll
    for (int i = 0; i < 4; i++)
        t[ty + i * 8][tx] = W[(size_t)(k0 + ty + i * 8) * HIDDEN + n0 + tx];
    __syncthreads();
#pragma unroll
    for (int i = 0; i < 4; i++) {
        int nr = ty + i * 8;
        float v = t[tx][nr];
        bf16 h = __float2bfloat16_rn(v);
        bf16 l = __float2bfloat16_rn(v - __bfloat162float(h));
        s_whi[zoff + (size_t)(n0 + nr) * HIDDEN + k0 + tx] = h;
        s_wlo[zoff + (size_t)(n0 + nr) * HIDDEN + k0 + tx] = l;
    }
}

// ---------------------------------------------------------------------------
// Split-bf16 GEMM: C[4096x1024] = A @ Wt^T ; A,Wt row-major bf16 hi/lo.
// Block 128x128xBK32, 2-stage cp.async, 8 warps (warp tile 64x32), 2 CTAs/SM.
// (R8-proven configuration.)
// ---------------------------------------------------------------------------
#define GBK     32
#define GKITERS (HIDDEN / GBK)          // 32
#define GSTR    80                      // bytes per smem row (40 bf16, pad)
#define GT_B    (128 * GSTR)            // 10240 per matrix tile
#define OA_HI   0
#define OA_LO   GT_B
#define OB_HI   (2 * GT_B)
#define OB_LO   (3 * GT_B)
#define GSTAGE_B (4 * GT_B)             // 40960
#define GSMEM   (2 * GSTAGE_B)          // 81920 (x2 CTAs = 160K)

__device__ __forceinline__ void gemm_load_stage(
    uint32_t sb, const bf16* __restrict__ Ahi, const bf16* __restrict__ Alo,
    const bf16* __restrict__ Bhi, const bf16* __restrict__ Blo,
    int row0, int col0, int kc, int tid)
{
    const int k0 = kc * GBK;
#pragma unroll
    for (int i = 0; i < 2; i++) {
        int idx = tid + i * 256;        // 512 chunks per matrix
        int r = idx >> 2, c = idx & 3;  // r 0..127, c 0..3 (16B chunks)
        uint32_t so = (uint32_t)(r * GSTR + c * 16);
        size_t ga = (size_t)(row0 + r) * HIDDEN + k0 + c * 8;
        size_t gb = (size_t)(col0 + r) * HIDDEN + k0 + c * 8;
        cp16(sb + OA_HI + so, &Ahi[ga]);
        cp16(sb + OA_LO + so, &Alo[ga]);
        cp16(sb + OB_HI + so, &Bhi[gb]);
        cp16(sb + OB_LO + so, &Blo[gb]);
    }
}

__device__ __forceinline__ void gemm_body(
    const bf16* __restrict__ Ahi, const bf16* __restrict__ Alo,
    const bf16* __restrict__ Bhi, const bf16* __restrict__ Blo,
    bf16* __restrict__ OutHi, bf16* __restrict__ OutLo,   // mode qkv (permuted)
    float* __restrict__ OutF,                             // mode fp32 row-major
    float oscale)
{
    extern __shared__ __align__(16) char gsm[];
    const uint32_t sb0 = smem_u32(gsm);

    const int tid = threadIdx.x;        // 256 threads
    const int lane = tid & 31;
    const int wid = tid >> 5;           // 0..7
    const int g = lane >> 2, tig = lane & 3;
    const int warp_m = wid >> 2;        // 0..1 (64 rows)
    const int warp_n = wid & 3;         // 0..3 (32 cols)
    const int row0 = blockIdx.y * 128;
    const int col0 = blockIdx.x * 128;

    float acc[4][4][4];
#pragma unroll
    for (int mi = 0; mi < 4; mi++)
#pragma unroll
        for (int ni = 0; ni < 4; ni++)
#pragma unroll
            for (int e = 0; e < 4; e++) acc[mi][ni][e] = 0.f;

    gemm_load_stage(sb0, Ahi, Alo, Bhi, Blo, row0, col0, 0, tid);
    CP_COMMIT();

    const uint32_t a_row = (uint32_t)(((lane >> 3) & 1) * 8 + (lane & 7));
    const uint32_t a_cb  = (uint32_t)((lane >> 4) * 16);
    const uint32_t b_row = (uint32_t)((lane >> 4) * 8 + (lane & 7));
    const uint32_t b_cb  = (uint32_t)(((lane >> 3) & 1) * 16);

    for (int kc = 0; kc < GKITERS; kc++) {
        CP_WAIT0();
        __syncthreads();
        if (kc + 1 < GKITERS)
            gemm_load_stage(sb0 + ((kc + 1) & 1) * GSTAGE_B, Ahi, Alo, Bhi, Blo,
                            row0, col0, kc + 1, tid);
        CP_COMMIT();

        const uint32_t sb = sb0 + (kc & 1) * GSTAGE_B;
#pragma unroll
        for (int ks = 0; ks < 2; ks++) {           // two k16 slices
            const uint32_t cbA = (uint32_t)(ks * 32) + a_cb;
            const uint32_t cbB = (uint32_t)(ks * 32) + b_cb;
            uint32_t ah[4][4], al[4][4];
#pragma unroll
            for (int mi = 0; mi < 4; mi++) {
                uint32_t r = (uint32_t)(warp_m * 64 + mi * 16) + a_row;
                uint32_t ad = sb + r * GSTR + cbA;
                ldsm4(ah[mi][0], ah[mi][1], ah[mi][2], ah[mi][3], ad + OA_HI);
                ldsm4(al[mi][0], al[mi][1], al[mi][2], al[mi][3], ad + OA_LO);
            }
#pragma unroll
            for (int np = 0; np < 2; np++) {       // n16 pairs (32 cols)
                uint32_t n = (uint32_t)(warp_n * 32 + np * 16) + b_row;
                uint32_t bd = sb + n * GSTR + cbB;
                uint32_t h0, h1, h2, h3, l0, l1, l2, l3;
                ldsm4(h0, h1, h2, h3, bd + OB_HI);
                ldsm4(l0, l1, l2, l3, bd + OB_LO);
                uint32_t bh0[2] = {h0, h1}, bh1[2] = {h2, h3};
                uint32_t bl0[2] = {l0, l1}, bl1[2] = {l2, l3};
#pragma unroll
                for (int mi = 0; mi < 4; mi++) {
                    mma_bf16(acc[mi][np * 2],     ah[mi], bh0);
                    mma_bf16(acc[mi][np * 2],     ah[mi], bl0);
                    mma_bf16(acc[mi][np * 2],     al[mi], bh0);
                    mma_bf16(acc[mi][np * 2 + 1], ah[mi], bh1);
                    mma_bf16(acc[mi][np * 2 + 1], ah[mi], bl1);
                    mma_bf16(acc[mi][np * 2 + 1], al[mi], bh1);
                }
            }
        }
    }

    // epilogue
#pragma unroll
    for (int mi = 0; mi < 4; mi++) {
        int r = row0 + warp_m * 64 + mi * 16 + g;       // rows r, r+8
#pragma unroll
        for (int ni = 0; ni < 4; ni++) {
            int col = col0 + warp_n * 32 + ni * 8 + tig * 2;
            if (OutF) {
                *(float2*)&OutF[(size_t)r * HIDDEN + col] =
                    make_float2(acc[mi][ni][0], acc[mi][ni][1]);
                *(float2*)&OutF[(size_t)(r + 8) * HIDDEN + col] =
                    make_float2(acc[mi][ni][2], acc[mi][ni][3]);
            } else {
                int h = col >> 6, d = col & 63;
                int b0 = r >> 11, s0 = r & 2047;
                int b1 = (r + 8) >> 11, s1 = (r + 8) & 2047;
                size_t i0 = (((size_t)(b0 * HEADS + h)) * SEQ + s0) * HDIM + d;
                size_t i1 = (((size_t)(b1 * HEADS + h)) * SEQ + s1) * HDIM + d;
                uint32_t hi, lo;
                hilo2(acc[mi][ni][0] * oscale, acc[mi][ni][1] * oscale, hi, lo);
                *(uint32_t*)&OutHi[i0] = hi;  *(uint32_t*)&OutLo[i0] = lo;
                hilo2(acc[mi][ni][2] * oscale, acc[mi][ni][3] * oscale, hi, lo);
                *(uint32_t*)&OutHi[i1] = hi;  *(uint32_t*)&OutLo[i1] = lo;
            }
        }
    }
}

__global__ __launch_bounds__(256, 2) void gemm_qkv() {
    const int z = blockIdx.z;
    const size_t zoff = (size_t)z * HIDDEN * HIDDEN;
    bf16* oh = (z == 0) ? g_qhi : (z == 1) ? g_khi : g_vhi;
    bf16* ol = (z == 0) ? g_qlo : (z == 1) ? g_klo : g_vlo;
    float sc = (z == 0) ? QK_SCALE2 : 1.0f;   // fold softmax scale into Q
    gemm_body(s_xhi, s_xlo, s_whi + zoff, s_wlo + zoff, oh, ol, nullptr, sc);
}
__global__ __launch_bounds__(256, 2) void gemm_out(float* __restrict__ out) {
    const size_t zoff = (size_t)3 * HIDDEN * HIDDEN;
    gemm_body(g_ohi, g_olo, s_whi + zoff, s_wlo + zoff, nullptr, nullptr, out, 1.0f);
}

// ---------------------------------------------------------------------------
// Flash attention, split-bf16, Br=128, Bc=128, 8 warps, 2 KV buffers.
// Q pre-scaled by 0.125*log2(e); softmax in exp2 domain.
// Flat grid, globally heavy-first: bx = 15 - idx/32, bh = idx % 32.
// ---------------------------------------------------------------------------
#define FQ_B   (128 * 128)              // 16384 bytes per Q matrix
#define FKV_B  (128 * 128)              // 16384 per KV matrix (128 rows x 128B)
#define OQH    0
#define OQL    FQ_B
#define OKV    (2 * FQ_B)
#define FSTAGE_B (4 * FKV_B)            // KH,KL,VH,VL = 65536
#define FSMEM  (2 * FQ_B + 2 * FSTAGE_B)   // 163840

// 128B rows, XOR swizzle on the 16B column within the row
__device__ __forceinline__ uint32_t fsw(uint32_t r, uint32_t cb) {
    return r * 128u + ((((cb >> 4) ^ r) & 7u) << 4);
}

__global__ __launch_bounds__(256) void flash_tc()
{
    extern __shared__ __align__(16) char fsm[];
    const uint32_t sb = smem_u32(fsm);

    const int tid = threadIdx.x;
    const int lane = tid & 31;
    const int wid = tid >> 5;
    const int g = lane >> 2, tig = lane & 3;
    // globally heavy-first: first 148 CTAs are the heaviest diagonal blocks
    const int idx = (int)blockIdx.x;
    const int bh = idx & 31;
    const int bx = (SEQ / 128 - 1) - (idx >> 5);      // 15 .. 0
    const int q0 = bx * 128;
    const size_t bho = (size_t)bh * SEQ * HDIM;
    const int nt = bx + 1;

    // ---- prologue loads ----
    {
        const bf16* qsrc[2] = {g_qhi + bho, g_qlo + bho};
#pragma unroll
        for (int m = 0; m < 2; m++)
#pragma unroll
            for (int i = 0; i < 4; i++) {
                int ci = tid + i * 256;            // 1024 chunks
                int r = ci >> 3, c = ci & 7;
                cp16(sb + (m ? OQL : OQH) + fsw(r, c * 16),
                     qsrc[m] + (size_t)(q0 + r) * HDIM + c * 8);
            }
    }
    auto load_kv = [&](int t, int buf) {
        const int j0 = t * 128;
        const bf16* src[4] = {g_khi + bho, g_klo + bho, g_vhi + bho, g_vlo + bho};
        uint32_t base = sb + OKV + buf * FSTAGE_B;
#pragma unroll
        for (int m = 0; m < 4; m++)
#pragma unroll
            for (int i = 0; i < 4; i++) {
                int ci = tid + i * 256;            // 1024 chunks per matrix
                int r = ci >> 3, c = ci & 7;
                cp16(base + m * FKV_B + fsw(r, c * 16),
                     src[m] + (size_t)(j0 + r) * HDIM + c * 8);
            }
    };
    load_kv(0, 0);
    CP_COMMIT();                        // group: Q + KV0
    if (nt > 1) load_kv(1, 1);
    CP_COMMIT();                        // group: KV1 (possibly empty)

    const uint32_t a_row = (uint32_t)(((lane >> 3) & 1) * 8 + (lane & 7));
    const uint32_t a_cb  = (uint32_t)((lane >> 4) * 16);
    const uint32_t b_row = (uint32_t)((lane >> 4) * 8 + (lane & 7));
    const uint32_t b_cb  = (uint32_t)(((lane >> 3) & 1) * 16);
    const uint32_t q_row = (uint32_t)(wid * 16) + a_row;

    float m0 = -1e30f, m1 = -1e30f, l0 = 0.f, l1 = 0.f;
    float o[8][4];
#pragma unroll
    for (int dt = 0; dt < 8; dt++)
#pragma unroll
        for (int e = 0; e < 4; e++) o[dt][e] = 0.f;

    for (int t = 0; t < nt; t++) {
        CP_WAIT1();
        __syncthreads();
        const uint32_t kvb = sb + OKV + (t & 1) * FSTAGE_B;

        // ---- S = Q K^T (scores already in log2 domain via pre-scaled Q) ----
        float s[16][4];
#pragma unroll
        for (int j = 0; j < 16; j++)
#pragma unroll
            for (int e = 0; e < 4; e++) s[j][e] = 0.f;
#pragma unroll
        for (int ks = 0; ks < 4; ks++) {
            const uint32_t cbq = (uint32_t)(ks * 32) + a_cb;
            uint32_t qh[4], ql[4];
            ldsm4(qh[0], qh[1], qh[2], qh[3], sb + OQH + fsw(q_row, cbq));
            ldsm4(ql[0], ql[1], ql[2], ql[3], sb + OQL + fsw(q_row, cbq));
            const uint32_t cb = (uint32_t)(ks * 32) + b_cb;
#pragma unroll
            for (int np = 0; np < 8; np++) {
                uint32_t n = (uint32_t)(np * 16) + b_row;
                uint32_t h0, h1, h2, h3, l0r, l1r, l2r, l3r;
                ldsm4(h0, h1, h2, h3, kvb + 0 * FKV_B + fsw(n, cb));
                ldsm4(l0r, l1r, l2r, l3r, kvb + 1 * FKV_B + fsw(n, cb));
                uint32_t bh0[2] = {h0, h1}, bh1[2] = {h2, h3};
                uint32_t bl0[2] = {l0r, l1r}, bl1[2] = {l2r, l3r};
                mma_bf16(s[np * 2],     qh, bh0);
                mma_bf16(s[np * 2],     qh, bl0);
                mma_bf16(s[np * 2],     ql, bh0);
                mma_bf16(s[np * 2 + 1], qh, bh1);
                mma_bf16(s[np * 2 + 1], qh, bl1);
                mma_bf16(s[np * 2 + 1], ql, bh1);
            }
        }

        // ---- causal mask (diagonal tile only; uniform branch) ----
        if (t == bx) {
            const int j0 = t * 128;
            const int r0 = q0 + wid * 16 + g;
#pragma unroll
            for (int j = 0; j < 16; j++) {
#pragma unroll
                for (int e = 0; e < 4; e++) {
                    int col = j0 + j * 8 + tig * 2 + (e & 1);
                    int row = r0 + ((e >> 1) * 8);
                    if (col > row) s[j][e] = -1e9f;
                }
            }
        }

        // ---- online softmax (rows g and g+8), exp2 domain ----
        float mx0 = -1e30f, mx1 = -1e30f;
#pragma unroll
        for (int j = 0; j < 16; j++) {
            mx0 = fmaxf(mx0, fmaxf(s[j][0], s[j][1]));
            mx1 = fmaxf(mx1, fmaxf(s[j][2], s[j][3]));
        }
        mx0 = fmaxf(mx0, __shfl_xor_sync(0xffffffffu, mx0, 1));
        mx0 = fmaxf(mx0, __shfl_xor_sync(0xffffffffu, mx0, 2));
        mx1 = fmaxf(mx1, __shfl_xor_sync(0xffffffffu, mx1, 1));
        mx1 = fmaxf(mx1, __shfl_xor_sync(0xffffffffu, mx1, 2));
        float mn0 = fmaxf(m0, mx0), mn1 = fmaxf(m1, mx1);
        float al0 = exp2f(m0 - mn0), al1 = exp2f(m1 - mn1);
        float sum0 = 0.f, sum1 = 0.f;
#pragma unroll
        for (int j = 0; j < 16; j++) {
            s[j][0] = exp2f(s[j][0] - mn0); sum0 += s[j][0];
            s[j][1] = exp2f(s[j][1] - mn0); sum0 += s[j][1];
            s[j][2] = exp2f(s[j][2] - mn1); sum1 += s[j][2];
            s[j][3] = exp2f(s[j][3] - mn1); sum1 += s[j][3];
        }
        sum0 += __shfl_xor_sync(0xffffffffu, sum0, 1);
        sum0 += __shfl_xor_sync(0xffffffffu, sum0, 2);
        sum1 += __shfl_xor_sync(0xffffffffu, sum1, 1);
        sum1 += __shfl_xor_sync(0xffffffffu, sum1, 2);
        l0 = l0 * al0 + sum0;  m0 = mn0;
        l1 = l1 * al1 + sum1;  m1 = mn1;
#pragma unroll
        for (int dt = 0; dt < 8; dt++) {
            o[dt][0] *= al0; o[dt][1] *= al0;
            o[dt][2] *= al1; o[dt][3] *= al1;
        }

        // ---- O += P V ----
#pragma unroll
        for (int kp = 0; kp < 8; kp++) {
            uint32_t ph[4], pl[4];
            hilo2(s[2 * kp][0],     s[2 * kp][1],     ph[0], pl[0]);
            hilo2(s[2 * kp][2],     s[2 * kp][3],     ph[1], pl[1]);
            hilo2(s[2 * kp + 1][0], s[2 * kp + 1][1], ph[2], pl[2]);
            hilo2(s[2 * kp + 1][2], s[2 * kp + 1][3], ph[3], pl[3]);
            uint32_t kr = (uint32_t)(kp * 16) + a_row;     // kv row within tile
#pragma unroll
            for (int np = 0; np < 4; np++) {
                uint32_t cb = (uint32_t)(np * 32) + a_cb;  // d col bytes
                uint32_t v0, v1, v2, v3, w0, w1, w2, w3;
                ldsm4t(v0, v1, v2, v3, kvb + 2 * FKV_B + fsw(kr, cb));
                ldsm4t(w0, w1, w2, w3, kvb + 3 * FKV_B + fsw(kr, cb));
                uint32_t bh0[2] = {v0, v1}, bh1[2] = {v2, v3};
                uint32_t bl0[2] = {w0, w1}, bl1[2] = {w2, w3};
                mma_bf16(o[np * 2],     ph, bh0);
                mma_bf16(o[np * 2],     ph, bl0);
                mma_bf16(o[np * 2],     pl, bh0);
                mma_bf16(o[np * 2 + 1], ph, bh1);
                mma_bf16(o[np * 2 + 1], ph, bl1);
                mma_bf16(o[np * 2 + 1], pl, bh1);
            }
        }

        __syncthreads();
        if (t + 2 < nt) load_kv(t + 2, t & 1);
        CP_COMMIT();
    }

    // ---- epilogue: O/l -> bf16 hi/lo at [b][s][h*64+d] ----
    const int b = bh >> 4, h = bh & 15;
    const int s0 = q0 + wid * 16 + g;
    const float i0 = 1.f / l0, i1 = 1.f / l1;
#pragma unroll
    for (int dt = 0; dt < 8; dt++) {
        int d = dt * 8 + tig * 2;
        size_t base0 = ((size_t)(b * SEQ) + s0) * HIDDEN + h * HDIM + d;
        size_t base1 = base0 + (size_t)8 * HIDDEN;
        uint32_t hi, lo;
        hilo2(o[dt][0] * i0, o[dt][1] * i0, hi, lo);
        *(uint32_t*)&g_ohi[base0] = hi;  *(uint32_t*)&g_olo[base0] = lo;
        hilo2(o[dt][2] * i1, o[dt][3] * i1, hi, lo);
        *(uint32_t*)&g_ohi[base1] = hi;  *(uint32_t*)&g_olo[base1] = lo;
    }
}

// ---------------------------------------------------------------------------
// Launch
// ---------------------------------------------------------------------------
extern "C" void kernel_launch(void* const* d_in, const int* in_sizes, int n_in,
                              void* d_out, int out_size)
{
    const float* X  = (const float*)d_in[0];
    // d_in[1] = attention_mask (exact causal; applied analytically)
    const float* Wq = (const float*)d_in[2];
    const float* Wk = (const float*)d_in[3];
    const float* Wv = (const float*)d_in[4];
    const float* Wo = (const float*)d_in[5];
    float* out = (float*)d_out;

    cudaFuncSetAttribute(gemm_qkv, cudaFuncAttributeMaxDynamicSharedMemorySize, GSMEM);
    cudaFuncSetAttribute(gemm_out, cudaFuncAttributeMaxDynamicSharedMemorySize, GSMEM);
    cudaFuncSetAttribute(flash_tc, cudaFuncAttributeMaxDynamicSharedMemorySize, FSMEM);

    convert_x<<<NTOK * HIDDEN / 1024, 256>>>(X);
    transpose_w<<<dim3(32, 32, 4), dim3(32, 8)>>>(Wq, Wk, Wv, Wo);

    gemm_qkv<<<dim3(HIDDEN / 128, NTOK / 128, 3), 256, GSMEM>>>();

    flash_tc<<<(SEQ / 128) * BATCH * HEADS, 256, FSMEM>>>();

    gemm_out<<<dim3(HIDDEN / 128, NTOK / 128), 256, GSMEM>>>(out);
}